// round 12
// baseline (speedup 1.0000x reference)
#include <cuda_runtime.h>
#include <cuda_bf16.h>
#include <cstdint>

// Problem constants
#define B_   32
#define C_   96
#define HID_ 576
#define H_   28
#define W_   28
#define P_   784
#define NP_  25088

// ---------------- device scratch ----------------
__device__ __align__(16) int    g_qxt[NP_ * 12];              // [pix][12 ints] s4-packed (96 k-nibbles)
__device__ __align__(16) int8_t g_q1p[HID_ * B_ * 30 * 32];   // planar halo layout (bytes)
__device__ __align__(16) int    g_q2 [NP_ * 72];              // [pix][72 ints] s4-packed (576 nibbles)
__device__ __align__(16) int    g_qw1[HID_ * 12];             // [co][12 ints] s4-packed
__device__ __align__(16) int    g_qw3[C_ * 72];               // [co][72 ints] s4-packed
__device__ __align__(16) int    g_qw2r[HID_ * 4];
__device__ __align__(16) float  g_A1[HID_], g_B1[HID_];       // folded with 1/ax2
__device__ __align__(16) float  g_A2[HID_], g_B2[HID_];       // folded with 1/ax3
__device__ __align__(16) float  g_A3[C_],   g_B3[C_];
__device__ float g_c[4];   // [1]=min(6/ax2,7)  [3]=min(6/ax3,7)

// ---------------- helpers ----------------
// s4 MMA, K=64: A=4 regs, B=2 regs
__device__ __forceinline__ void mma64s4(int* c, int a0, int a1, int a2, int a3,
                                        int b0, int b1) {
    asm volatile("mma.sync.aligned.m16n8k64.row.col.s32.s4.s4.s32 "
        "{%0,%1,%2,%3}, {%4,%5,%6,%7}, {%8,%9}, {%0,%1,%2,%3};"
        : "+r"(c[0]), "+r"(c[1]), "+r"(c[2]), "+r"(c[3])
        : "r"(a0), "r"(a1), "r"(a2), "r"(a3), "r"(b0), "r"(b1));
}
// s4 MMA, K=32: A=2 regs, B=1 reg
__device__ __forceinline__ void mma32s4(int* c, int a0, int a1, int b0) {
    asm volatile("mma.sync.aligned.m16n8k32.row.col.s32.s4.s4.s32 "
        "{%0,%1,%2,%3}, {%4,%5}, {%6}, {%0,%1,%2,%3};"
        : "+r"(c[0]), "+r"(c[1]), "+r"(c[2]), "+r"(c[3])
        : "r"(a0), "r"(a1), "r"(b0));
}
__device__ __forceinline__ uint32_t smem_u32(const void* p) {
    uint32_t a;
    asm("{ .reg .u64 t; cvta.to.shared.u64 t, %1; cvt.u32.u64 %0, t; }" : "=r"(a) : "l"(p));
    return a;
}
__device__ __forceinline__ void cpa16(uint32_t s, const void* g) {
    asm volatile("cp.async.cg.shared.global [%0], [%1], 16;" :: "r"(s), "l"(g));
}
#define CPCOMMIT() asm volatile("cp.async.commit_group;" ::: "memory")
#define CPWAIT0()  asm volatile("cp.async.wait_group 0;" ::: "memory")

__device__ __forceinline__ int dpw(int lo, int hi, int sel, int w, int acc) {
    return __dp4a((int)__byte_perm((unsigned)lo, (unsigned)hi, (unsigned)sel), w, acc);
}
// folded epilogue: rint(clamp(acc*A + B, 0, cm))
__device__ __forceinline__ int bnq(int acc, float A, float Bv, float cm) {
    float f = fmaf((float)acc, A, Bv);
    f = fminf(fmaxf(f, 0.0f), cm);
    return (int)rintf(f);
}
// pack 4 bytes (low nibbles) into 16 bits: [b0|b1<<4, b2|b3<<4]
__device__ __forceinline__ int nib4(int v) {
    int x = v & 0x0F0F0F0F;
    x = (x | (x >> 4)) & 0x00FF00FF;
    x = (x | (x >> 8)) & 0x0000FFFF;
    return x;
}

// ---------------- kernel: prep = setup + halo zero + quantize/pack x ----------------
__global__ void k_prep(const float* __restrict__ x,
                       const float* w1, const float* w2, const float* w3,
                       const float* aw1, const float* ax1,
                       const float* g1, const float* b1, const float* m1, const float* v1,
                       const float* aw2, const float* ax2,
                       const float* g2, const float* b2, const float* m2, const float* v2,
                       const float* aw3, const float* ax3,
                       const float* g3, const float* b3, const float* m3, const float* v3)
{
    __shared__ int8_t sq[C_ * 36];
    int t   = threadIdx.x;
    int tid = blockIdx.x * 256 + t;
    int nt  = gridDim.x * 256;
    float a1 = aw1[0], a2 = aw2[0], a3 = aw3[0];

    if (tid < HID_ * B_) {
        int4* p4 = reinterpret_cast<int4*>(g_q1p + (size_t)tid * 960);
        int4 z = make_int4(0, 0, 0, 0);
        p4[0] = z; p4[1] = z;
        p4[58] = z; p4[59] = z;
        int* pi = reinterpret_cast<int*>(g_q1p + (size_t)tid * 960);
#pragma unroll
        for (int r = 1; r < 29; r++) pi[r * 8 + 7] = 0;
    }
    // pack w1: [co][12 ints]
    {
        float ra = 1.0f / a1;
        for (int i = tid; i < HID_ * 12; i += nt) {
            int co = i / 12, ii = i % 12;
            int acc = 0;
#pragma unroll
            for (int l = 0; l < 8; l++) {
                int q = (int)rintf(fminf(fmaxf(w1[co * 96 + ii * 8 + l] * ra, -8.0f), 7.0f));
                acc |= (q & 15) << (4 * l);
            }
            g_qw1[i] = acc;
        }
    }
    // pack w3: [co][72 ints]
    {
        float ra = 1.0f / a3;
        for (int i = tid; i < C_ * 72; i += nt) {
            int co = i / 72, ii = i % 72;
            int acc = 0;
#pragma unroll
            for (int l = 0; l < 8; l++) {
                int q = (int)rintf(fminf(fmaxf(w3[co * 576 + ii * 8 + l] * ra, -8.0f), 7.0f));
                acc |= (q & 15) << (4 * l);
            }
            g_qw3[i] = acc;
        }
    }
    for (int c = tid; c < HID_; c += nt) {
        int q[9];
#pragma unroll
        for (int tp = 0; tp < 9; tp++)
            q[tp] = (int)rintf(fminf(fmaxf(w2[c * 9 + tp] / a2, -8.0f), 7.0f));
#pragma unroll
        for (int r = 0; r < 3; r++)
            g_qw2r[c * 4 + r] = (q[3*r] & 255) | ((q[3*r+1] & 255) << 8) | ((q[3*r+2] & 255) << 16);
        float r2 = 1.0f / ax2[0];
        float r3 = 1.0f / ax3[0];
        float s1 = g1[c] / sqrtf(v1[c] + 1e-5f);
        g_A1[c] = ax1[0] * a1 * s1 * r2;
        g_B1[c] = (b1[c] - m1[c] * s1) * r2;
        float s2 = g2[c] / sqrtf(v2[c] + 1e-5f);
        g_A2[c] = ax2[0] * a2 * s2 * r3;
        g_B2[c] = (b2[c] - m2[c] * s2) * r3;
    }
    for (int c = tid; c < C_; c += nt) {
        float s3 = g3[c] / sqrtf(v3[c] + 1e-5f);
        g_A3[c] = ax3[0] * a3 * s3;
        g_B3[c] = b3[c] - m3[c] * s3;
    }
    if (tid == 0) {
        g_c[1] = fminf(6.0f / ax2[0], 7.0f);
        g_c[3] = fminf(6.0f / ax3[0], 7.0f);
    }

    // quantize + transpose + nibble-pack x: per block 32 pixels of one image
    int n  = blockIdx.x / 25;
    int p0 = (blockIdx.x % 25) * 32;
    float rax = 1.0f / ax1[0];
#pragma unroll
    for (int r = 0; r < 12; r++) {
        int idx = t + r * 256;
        int c = idx >> 5, j = idx & 31;
        int p = p0 + j;
        float val = (p < P_) ? x[(n * C_ + c) * P_ + p] : 0.0f;
        float q = rintf(fminf(fmaxf(val * rax, -8.0f), 7.0f));
        sq[c * 36 + j] = (int8_t)(int)q;
    }
    __syncthreads();
#pragma unroll
    for (int r = 0; r < 2; r++) {
        int idx = t + r * 256;            // 384 = 32px * 12 ints
        if (idx < 384) {
            int j = idx / 12, ii = idx % 12;
            int p = p0 + j;
            if (p < P_) {
                int acc = 0;
#pragma unroll
                for (int l = 0; l < 8; l++)
                    acc |= ((int)sq[(ii * 8 + l) * 36 + j] & 15) << (4 * l);
                g_qxt[(n * P_ + p) * 12 + ii] = acc;
            }
        }
    }
}

// ---------------- kernel: conv1 via s4 mma, single wave, 4 pix-tiles/block ----------------
// smem ints: A0 @0 [112][20], A1 @2240, W @4480 [72][20], stage bytes @5920 (2088 ints), floats @8008
#define C1A(buf) ((buf) * 2240)
#define C1W      4480
#define C1STG    5920
#define C1FLT    8008
__global__ __launch_bounds__(224, 4) void k_conv1m()
{
    __shared__ __align__(16) int sU[8152];
    uint32_t sb = smem_u32(sU);
    int8_t* sS = reinterpret_cast<int8_t*>(sU + C1STG);
    float* sAf = reinterpret_cast<float*>(sU + C1FLT);
    float* sBf = sAf + 72;

    int t = threadIdx.x, w = t >> 5, lane = t & 31;
    int q = lane >> 2, rr = lane & 3;
    int tile0 = blockIdx.x * 4;
    int co0   = blockIdx.y * 72;

    // W once (216 int4) + A tile0 (336 int4), async
    {
        if (t < 216) {
            int r = t / 3, c = t % 3;
            cpa16(sb + (uint32_t)(C1W + r * 20 + c * 4) * 4,
                  g_qw1 + (size_t)(co0 + r) * 12 + c * 4);
        }
#pragma unroll
        for (int it = 0; it < 2; it++) {
            int i = t + it * 224;
            if (i < 336) {
                int r = i / 3, c = i % 3;
                cpa16(sb + (uint32_t)(C1A(0) + r * 20 + c * 4) * 4,
                      g_qxt + (size_t)(tile0 * 112 + r) * 12 + c * 4);
            }
        }
        CPCOMMIT();
    }
    if (t < 72) { sAf[t] = g_A1[co0 + t]; sBf[t] = g_B1[co0 + t]; }
    float cm = g_c[1];
    CPWAIT0();
    __syncthreads();

#pragma unroll
    for (int tl = 0; tl < 4; tl++) {
        int buf = tl & 1;
        if (tl < 3) {
#pragma unroll
            for (int it = 0; it < 2; it++) {
                int i = t + it * 224;
                if (i < 336) {
                    int r = i / 3, c = i % 3;
                    cpa16(sb + (uint32_t)(C1A(buf ^ 1) + r * 20 + c * 4) * 4,
                          g_qxt + (size_t)((tile0 + tl + 1) * 112 + r) * 12 + c * 4);
                }
            }
            CPCOMMIT();
        }

        int acc[9][4];
#pragma unroll
        for (int nb = 0; nb < 9; nb++)
#pragma unroll
            for (int j = 0; j < 4; j++) acc[nb][j] = 0;

        const int* ap = sU + C1A(buf) + (w * 16 + q) * 20 + rr;
        int a0 = ap[0], a1 = ap[160], a2 = ap[4], a3 = ap[164];   // k 0..63
        int a4 = ap[8], a5 = ap[168];                              // k 64..95
#pragma unroll
        for (int nb = 0; nb < 9; nb++) {
            const int* bp = sU + C1W + (nb * 8 + q) * 20 + rr;
            mma64s4(acc[nb], a0, a1, a2, a3, bp[0], bp[4]);
            mma32s4(acc[nb], a4, a5, bp[8]);
        }

        // stage quantized bytes [co][pix]
        int pr0 = w * 16 + q, pr1 = pr0 + 8;
#pragma unroll
        for (int nb = 0; nb < 9; nb++) {
            int ca = nb * 8 + rr * 2, cb = ca + 1;
            sS[ca * 116 + pr0] = (int8_t)bnq(acc[nb][0], sAf[ca], sBf[ca], cm);
            sS[cb * 116 + pr0] = (int8_t)bnq(acc[nb][1], sAf[cb], sBf[cb], cm);
            sS[ca * 116 + pr1] = (int8_t)bnq(acc[nb][2], sAf[ca], sBf[ca], cm);
            sS[cb * 116 + pr1] = (int8_t)bnq(acc[nb][3], sAf[cb], sBf[cb], cm);
        }
        __syncthreads();

        // coalesced planar store: 72 co x 4 rows x 7 ints = 2016 ints
        int pix0 = (tile0 + tl) * 112;
        int n = pix0 / P_;
        int yy = (pix0 % P_) / W_;
#pragma unroll
        for (int it = 0; it < 9; it++) {
            int i = t + it * 224;
            int co = i / 28, rem = i % 28, seg = rem / 7, wd = rem % 7;
            int val = *reinterpret_cast<const int*>(&sS[co * 116 + seg * 28 + wd * 4]);
            *reinterpret_cast<int*>(
                &g_q1p[(size_t)(co0 + co) * 30720 + n * 960 + (yy + seg + 1) * 32 + wd * 4]) = val;
        }
        if (tl < 3) CPWAIT0();
        __syncthreads();
    }
}

// ---------------- kernel: depthwise 3x3 + bn2 + relu6 + quant -> s4-packed g_q2 ----------------
__global__ __launch_bounds__(288) void k_dw()
{
    __shared__ __align__(16) int s_in[72 * 52];
    __shared__ __align__(16) int s_out[2016];
    int t  = threadIdx.x;
    int b  = blockIdx.x;
    int cg = b & 7;
    int s  = (b >> 3) % 7;
    int n  = b / 56;
    int c0 = cg * 72;

    const int4* g4 = reinterpret_cast<const int4*>(g_q1p);
    int4* s4 = reinterpret_cast<int4*>(s_in);
#pragma unroll
    for (int it = 0; it < 3; it++) {
        int idx = t + it * 288;
        int c = idx / 12, r4 = idx % 12;
        s4[c * 13 + r4] = g4[((c0 + c) * 32 + n) * 60 + s * 8 + r4];
    }
    __syncthreads();

    int c = t % 72, y = t / 72;
    int gc = c0 + c;
    int w0 = g_qw2r[gc * 4 + 0];
    int w1 = g_qw2r[gc * 4 + 1];
    int w2 = g_qw2r[gc * 4 + 2];
    float A = g_A2[gc], Bv = g_B2[gc];
    float cm = g_c[3];

    const int4* sb = s4 + c * 13 + y * 2;
    int4 t0 = sb[0], t1 = sb[1], t2 = sb[2], t3 = sb[3], t4 = sb[4], t5 = sb[5];
    int r0[8] = {t0.x, t0.y, t0.z, t0.w, t1.x, t1.y, t1.z, t1.w};
    int r1[8] = {t2.x, t2.y, t2.z, t2.w, t3.x, t3.y, t3.z, t3.w};
    int r2[8] = {t4.x, t4.y, t4.z, t4.w, t5.x, t5.y, t5.z, t5.w};

    int8_t* so = reinterpret_cast<int8_t*>(s_out);
#pragma unroll
    for (int j = 0; j < 7; j++) {
        int p0 = j ? r0[j - 1] : 0, m0 = r0[j], q0 = r0[j + 1];
        int p1 = j ? r1[j - 1] : 0, m1 = r1[j], q1 = r1[j + 1];
        int p2 = j ? r2[j - 1] : 0, m2 = r2[j], q2 = r2[j + 1];
        int a0 = 0, a1 = 0, a2 = 0, a3 = 0;
        a0 = dpw(p0, m0, 0x5543, w0, a0);
        a1 = dpw(p0, m0, 0x6654, w0, a1);
        a2 = dpw(p0, m0, 0x7765, w0, a2);
        a3 = dpw(m0, q0, 0x4432, w0, a3);
        a0 = dpw(p1, m1, 0x5543, w1, a0);
        a1 = dpw(p1, m1, 0x6654, w1, a1);
        a2 = dpw(p1, m1, 0x7765, w1, a2);
        a3 = dpw(m1, q1, 0x4432, w1, a3);
        a0 = dpw(p2, m2, 0x5543, w2, a0);
        a1 = dpw(p2, m2, 0x6654, w2, a1);
        a2 = dpw(p2, m2, 0x7765, w2, a2);
        a3 = dpw(m2, q2, 0x4432, w2, a3);

        int pixb = (y * 28 + j * 4) * 72 + c;
        so[pixb      ] = (int8_t)bnq(a0, A, Bv, cm);
        so[pixb + 72 ] = (int8_t)bnq(a1, A, Bv, cm);
        so[pixb + 144] = (int8_t)bnq(a2, A, Bv, cm);
        so[pixb + 216] = (int8_t)bnq(a3, A, Bv, cm);
    }
    __syncthreads();

    // pack byte-pairs -> nibbles and store: [pix][72 ints], this block covers ints cg*9..cg*9+8
    int pbase = n * P_ + s * 112;
#pragma unroll
    for (int it = 0; it < 4; it++) {
        int idx = t + it * 288;               // 1008 = 112 px * 9 ints
        if (idx < 1008) {
            int pix = idx / 9, k = idx % 9;
            int v0 = s_out[pix * 18 + k * 2];
            int v1 = s_out[pix * 18 + k * 2 + 1];
            g_q2[(size_t)(pbase + pix) * 72 + cg * 9 + k] = nib4(v0) | (nib4(v1) << 16);
        }
    }
}

// ---------------- kernel: conv3 via s4 mma — W resident, A direct LDG, no K-loop barriers ----------------
// smem ints: W [48][76] @0 (3648), stage fp32 [48][113] @3648 (5424), floats @9072 (96)
#define C3W_STRIDE 76
#define C3STG 3648
#define C3FLT 9072
__global__ __launch_bounds__(224, 4) void k_conv3m(const float* __restrict__ x,
                                                   float* __restrict__ out)
{
    __shared__ __align__(16) int sU[9168];
    uint32_t sb = smem_u32(sU);
    float* stg = reinterpret_cast<float*>(sU + C3STG);
    float* sAf = reinterpret_cast<float*>(sU + C3FLT);
    float* sBf = sAf + 48;

    int t = threadIdx.x, w = t >> 5, lane = t & 31;
    int q = lane >> 2, rr = lane & 3;
    int pix0 = blockIdx.x * 112;
    int co0  = blockIdx.y * 48;

    // load all of W (48 x 288B = 864 int4) once, async
    {
#pragma unroll
        for (int it = 0; it < 4; it++) {
            int i = t + it * 224;
            if (i < 864) {
                int r = i / 18, c = i % 18;
                cpa16(sb + (uint32_t)(r * C3W_STRIDE + c * 4) * 4,
                      g_qw3 + (size_t)(co0 + r) * 72 + c * 4);
            }
        }
        CPCOMMIT();
    }
    if (t < 48) { sAf[t] = g_A3[co0 + t]; sBf[t] = g_B3[co0 + t]; }
    CPWAIT0();
    __syncthreads();

    int acc[6][4];
#pragma unroll
    for (int nb = 0; nb < 6; nb++)
#pragma unroll
        for (int j = 0; j < 4; j++) acc[nb][j] = 0;

    // A straight from global (L2-resident packed g_q2)
    const int* gA = g_q2 + (size_t)(pix0 + w * 16 + q) * 72 + rr;

#pragma unroll
    for (int ch = 0; ch < 9; ch++) {
        int a0 = __ldg(gA + ch * 8);
        int a1 = __ldg(gA + ch * 8 + 576);      // +8 rows * 72
        int a2 = __ldg(gA + ch * 8 + 4);
        int a3 = __ldg(gA + ch * 8 + 580);
#pragma unroll
        for (int nb = 0; nb < 6; nb++) {
            const int* bp = sU + (nb * 8 + q) * C3W_STRIDE + rr + ch * 8;
            mma64s4(acc[nb], a0, a1, a2, a3, bp[0], bp[4]);
        }
    }
    __syncthreads();

    // stage fp32 [co][pix] stride 113
    int pr0 = w * 16 + q, pr1 = pr0 + 8;
#pragma unroll
    for (int nb = 0; nb < 6; nb++) {
        int ca = nb * 8 + rr * 2, cb = ca + 1;
        stg[ca * 113 + pr0] = (float)acc[nb][0];
        stg[cb * 113 + pr0] = (float)acc[nb][1];
        stg[ca * 113 + pr1] = (float)acc[nb][2];
        stg[cb * 113 + pr1] = (float)acc[nb][3];
    }
    __syncthreads();

    int n = pix0 / P_;
    int prow = pix0 % P_;
#pragma unroll
    for (int it = 0; it < 24; it++) {
        int i = t + it * 224;
        int co = i / 112, p = i % 112;
        int off = (n * C_ + co0 + co) * P_ + prow + p;
        out[off] = x[off] + fmaf(stg[co * 113 + p], sAf[co], sBf[co]);
    }
}

// ---------------- launch ----------------
extern "C" void kernel_launch(void* const* d_in, const int* in_sizes, int n_in,
                              void* d_out, int out_size)
{
    const float* x   = (const float*)d_in[0];
    const float* w1  = (const float*)d_in[1];
    const float* w2  = (const float*)d_in[2];
    const float* w3  = (const float*)d_in[3];
    const float* aw1 = (const float*)d_in[4];
    const float* ax1 = (const float*)d_in[5];
    const float* g1  = (const float*)d_in[6];
    const float* b1  = (const float*)d_in[7];
    const float* m1  = (const float*)d_in[8];
    const float* v1  = (const float*)d_in[9];
    const float* aw2 = (const float*)d_in[10];
    const float* ax2 = (const float*)d_in[11];
    const float* g2  = (const float*)d_in[12];
    const float* b2  = (const float*)d_in[13];
    const float* m2  = (const float*)d_in[14];
    const float* v2  = (const float*)d_in[15];
    const float* aw3 = (const float*)d_in[16];
    const float* ax3 = (const float*)d_in[17];
    const float* g3  = (const float*)d_in[18];
    const float* b3  = (const float*)d_in[19];
    const float* m3  = (const float*)d_in[20];
    const float* v3  = (const float*)d_in[21];
    float* out = (float*)d_out;

    k_prep<<<B_ * 25, 256>>>(x, w1, w2, w3, aw1, ax1, g1, b1, m1, v1,
                             aw2, ax2, g2, b2, m2, v2, aw3, ax3, g3, b3, m3, v3);
    k_conv1m<<<dim3(56, 8), 224>>>();
    k_dw<<<1792, 288>>>();
    k_conv3m<<<dim3(NP_ / 112, 2), 224>>>(x, out);
}

// round 13
// speedup vs baseline: 1.8572x; 1.8572x over previous
#include <cuda_runtime.h>
#include <cuda_bf16.h>
#include <cstdint>

// Problem constants
#define B_   32
#define C_   96
#define HID_ 576
#define H_   28
#define W_   28
#define P_   784
#define NP_  25088

// NOTE: all GEMM operand int-streams use a k-interleaved order within each
// 8-int (k=32-byte) group: stored[2m] = orig[m], stored[2m+1] = orig[m+4].
// Fragment lanes then read their (rr, rr+4) pair as ONE 8-byte load at 2rr.

// ---------------- device scratch ----------------
__device__ __align__(16) int    g_qxt[NP_ * 24];              // [pix][24 ints] permuted
__device__ __align__(16) int8_t g_q1p[HID_ * B_ * 30 * 32];   // planar halo layout
__device__ __align__(16) int    g_q2 [NP_ * 144];             // [pix][144 ints] permuted
__device__ __align__(16) int    g_qw1[HID_ * 24];             // [co][24 ints] permuted
__device__ __align__(16) int    g_qw3[C_ * 144];              // [co][144 ints] permuted
__device__ __align__(16) int    g_qw2r[HID_ * 4];
__device__ __align__(16) float  g_A1[HID_], g_B1[HID_];       // folded with 1/ax2
__device__ __align__(16) float  g_A2[HID_], g_B2[HID_];       // folded with 1/ax3
__device__ __align__(16) float  g_A3[C_],   g_B3[C_];
__device__ float g_c[4];   // [1]=min(6/ax2,7)  [3]=min(6/ax3,7)

// ---------------- helpers ----------------
__device__ __forceinline__ void mma8(int* c, int a0, int a1, int a2, int a3,
                                     int b0, int b1) {
    asm volatile("mma.sync.aligned.m16n8k32.row.col.s32.s8.s8.s32 "
        "{%0,%1,%2,%3}, {%4,%5,%6,%7}, {%8,%9}, {%0,%1,%2,%3};"
        : "+r"(c[0]), "+r"(c[1]), "+r"(c[2]), "+r"(c[3])
        : "r"(a0), "r"(a1), "r"(a2), "r"(a3), "r"(b0), "r"(b1));
}
__device__ __forceinline__ uint32_t smem_u32(const void* p) {
    uint32_t a;
    asm("{ .reg .u64 t; cvta.to.shared.u64 t, %1; cvt.u32.u64 %0, t; }" : "=r"(a) : "l"(p));
    return a;
}
__device__ __forceinline__ void cpa16(uint32_t s, const void* g) {
    asm volatile("cp.async.cg.shared.global [%0], [%1], 16;" :: "r"(s), "l"(g));
}
#define CPCOMMIT() asm volatile("cp.async.commit_group;" ::: "memory")
#define CPWAIT0()  asm volatile("cp.async.wait_group 0;" ::: "memory")

__device__ __forceinline__ int dpw(int lo, int hi, int sel, int w, int acc) {
    return __dp4a((int)__byte_perm((unsigned)lo, (unsigned)hi, (unsigned)sel), w, acc);
}
__device__ __forceinline__ int bnq(int acc, float A, float Bv, float cm) {
    float f = fmaf((float)acc, A, Bv);
    f = fminf(fmaxf(f, 0.0f), cm);
    return (int)rintf(f);
}
// gather source index for interleaved store position j within an 8-group
__device__ __forceinline__ int kperm_src(int j) {
    return (j >> 1) + (j & 1) * 4;
}

// ---------------- kernel: prep = setup + halo zero + quantize/pack x ----------------
__global__ void k_prep(const float* __restrict__ x,
                       const float* w1, const float* w2, const float* w3,
                       const float* aw1, const float* ax1,
                       const float* g1, const float* b1, const float* m1, const float* v1,
                       const float* aw2, const float* ax2,
                       const float* g2, const float* b2, const float* m2, const float* v2,
                       const float* aw3, const float* ax3,
                       const float* g3, const float* b3, const float* m3, const float* v3)
{
    __shared__ int8_t sq[C_ * 36];
    int t   = threadIdx.x;
    int tid = blockIdx.x * 256 + t;
    int nt  = gridDim.x * 256;
    float a1 = aw1[0], a2 = aw2[0], a3 = aw3[0];

    if (tid < HID_ * B_) {
        int4* p4 = reinterpret_cast<int4*>(g_q1p + (size_t)tid * 960);
        int4 z = make_int4(0, 0, 0, 0);
        p4[0] = z; p4[1] = z;
        p4[58] = z; p4[59] = z;
        int* pi = reinterpret_cast<int*>(g_q1p + (size_t)tid * 960);
#pragma unroll
        for (int r = 1; r < 29; r++) pi[r * 8 + 7] = 0;
    }
    // pack w1 -> [co][24 ints], k-interleaved
    {
        float ra = 1.0f / a1;
        for (int i = tid; i < HID_ * 24; i += nt) {
            int co = i / 24, ii = i % 24;
            int o = (ii & ~7) + kperm_src(ii & 7);
            int acc = 0;
#pragma unroll
            for (int l = 0; l < 4; l++) {
                int q = (int)rintf(fminf(fmaxf(w1[co * 96 + o * 4 + l] * ra, -8.0f), 7.0f));
                acc |= (q & 255) << (8 * l);
            }
            g_qw1[i] = acc;
        }
    }
    // pack w3 -> [co][144 ints], k-interleaved
    {
        float ra = 1.0f / a3;
        for (int i = tid; i < C_ * 144; i += nt) {
            int co = i / 144, ii = i % 144;
            int o = (ii & ~7) + kperm_src(ii & 7);
            int acc = 0;
#pragma unroll
            for (int l = 0; l < 4; l++) {
                int q = (int)rintf(fminf(fmaxf(w3[co * 576 + o * 4 + l] * ra, -8.0f), 7.0f));
                acc |= (q & 255) << (8 * l);
            }
            g_qw3[i] = acc;
        }
    }
    for (int c = tid; c < HID_; c += nt) {
        int q[9];
#pragma unroll
        for (int tp = 0; tp < 9; tp++)
            q[tp] = (int)rintf(fminf(fmaxf(w2[c * 9 + tp] / a2, -8.0f), 7.0f));
#pragma unroll
        for (int r = 0; r < 3; r++)
            g_qw2r[c * 4 + r] = (q[3*r] & 255) | ((q[3*r+1] & 255) << 8) | ((q[3*r+2] & 255) << 16);
        float r2 = 1.0f / ax2[0];
        float r3 = 1.0f / ax3[0];
        float s1 = g1[c] / sqrtf(v1[c] + 1e-5f);
        g_A1[c] = ax1[0] * a1 * s1 * r2;
        g_B1[c] = (b1[c] - m1[c] * s1) * r2;
        float s2 = g2[c] / sqrtf(v2[c] + 1e-5f);
        g_A2[c] = ax2[0] * a2 * s2 * r3;
        g_B2[c] = (b2[c] - m2[c] * s2) * r3;
    }
    for (int c = tid; c < C_; c += nt) {
        float s3 = g3[c] / sqrtf(v3[c] + 1e-5f);
        g_A3[c] = ax3[0] * a3 * s3;
        g_B3[c] = b3[c] - m3[c] * s3;
    }
    if (tid == 0) {
        g_c[1] = fminf(6.0f / ax2[0], 7.0f);
        g_c[3] = fminf(6.0f / ax3[0], 7.0f);
    }

    // quantize + transpose + interleave x: per block 32 pixels of one image
    int n  = blockIdx.x / 25;
    int p0 = (blockIdx.x % 25) * 32;
    float rax = 1.0f / ax1[0];
#pragma unroll
    for (int r = 0; r < 12; r++) {
        int idx = t + r * 256;
        int c = idx >> 5, j = idx & 31;
        int p = p0 + j;
        float val = (p < P_) ? x[(n * C_ + c) * P_ + p] : 0.0f;
        float q = rintf(fminf(fmaxf(val * rax, -8.0f), 7.0f));
        sq[c * 36 + j] = (int8_t)(int)q;
    }
    __syncthreads();
#pragma unroll
    for (int r = 0; r < 3; r++) {
        int idx = t + r * 256;            // 768 = 32px * 24 ints
        int j = idx / 24, ii = idx % 24;
        int p = p0 + j;
        if (p < P_) {
            int o = (ii & ~7) + kperm_src(ii & 7);
            int b0 = (int)sq[(o * 4 + 0) * 36 + j] & 255;
            int b1v = (int)sq[(o * 4 + 1) * 36 + j] & 255;
            int b2v = (int)sq[(o * 4 + 2) * 36 + j] & 255;
            int b3v = (int)sq[(o * 4 + 3) * 36 + j] & 255;
            g_qxt[(n * P_ + p) * 24 + ii] = b0 | (b1v << 8) | (b2v << 16) | (b3v << 24);
        }
    }
}

// ---------------- kernel: conv1 via mma.sync, single wave, 4 pix-tiles/block ----------------
// smem ints: A0 @0 [112][28], A1 @3136, W @6272 [72][28], stage @8288 (2088), floats @10376
#define C1A(buf) ((buf) * 3136)
#define C1W      6272
#define C1STG    8288
#define C1FLT    10376
__global__ __launch_bounds__(224, 4) void k_conv1m()
{
    __shared__ __align__(16) int sU[10520];
    uint32_t sb = smem_u32(sU);
    int8_t* sS = reinterpret_cast<int8_t*>(sU + C1STG);
    float* sAf = reinterpret_cast<float*>(sU + C1FLT);
    float* sBf = sAf + 72;

    int t = threadIdx.x, w = t >> 5, lane = t & 31;
    int q = lane >> 2, rr = lane & 3;
    int tile0 = blockIdx.x * 4;
    int co0   = blockIdx.y * 72;

    {
#pragma unroll
        for (int it = 0; it < 2; it++) {
            int i = t + it * 224;
            if (i < 432) {
                int r = i / 6, c = i % 6;
                cpa16(sb + (uint32_t)(C1W + r * 28 + c * 4) * 4,
                      g_qw1 + (size_t)(co0 + r) * 24 + c * 4);
            }
        }
#pragma unroll
        for (int it = 0; it < 3; it++) {
            int i = t + it * 224;
            int r = i / 6, c = i % 6;
            cpa16(sb + (uint32_t)(C1A(0) + r * 28 + c * 4) * 4,
                  g_qxt + (size_t)(tile0 * 112 + r) * 24 + c * 4);
        }
        CPCOMMIT();
    }
    if (t < 72) { sAf[t] = g_A1[co0 + t]; sBf[t] = g_B1[co0 + t]; }
    float cm = g_c[1];
    CPWAIT0();
    __syncthreads();

#pragma unroll
    for (int tl = 0; tl < 4; tl++) {
        int buf = tl & 1;
        if (tl < 3) {
#pragma unroll
            for (int it = 0; it < 3; it++) {
                int i = t + it * 224;
                int r = i / 6, c = i % 6;
                cpa16(sb + (uint32_t)(C1A(buf ^ 1) + r * 28 + c * 4) * 4,
                      g_qxt + (size_t)((tile0 + tl + 1) * 112 + r) * 24 + c * 4);
            }
            CPCOMMIT();
        }

        int acc[9][4];
#pragma unroll
        for (int nb = 0; nb < 9; nb++)
#pragma unroll
            for (int j = 0; j < 4; j++) acc[nb][j] = 0;

        const int* abase = sU + C1A(buf) + (w * 16 + q) * 28 + 2 * rr;
#pragma unroll
        for (int k = 0; k < 3; k++) {
            int2 lo = *reinterpret_cast<const int2*>(abase + k * 8);           // (a0, a2)
            int2 hi = *reinterpret_cast<const int2*>(abase + 8 * 28 + k * 8);  // (a1, a3)
#pragma unroll
            for (int nb = 0; nb < 9; nb++) {
                int2 bb = *reinterpret_cast<const int2*>(
                    sU + C1W + (nb * 8 + q) * 28 + 2 * rr + k * 8);
                mma8(acc[nb], lo.x, hi.x, lo.y, hi.y, bb.x, bb.y);
            }
        }

        int pr0 = w * 16 + q, pr1 = pr0 + 8;
#pragma unroll
        for (int nb = 0; nb < 9; nb++) {
            int ca = nb * 8 + rr * 2, cb = ca + 1;
            sS[ca * 116 + pr0] = (int8_t)bnq(acc[nb][0], sAf[ca], sBf[ca], cm);
            sS[cb * 116 + pr0] = (int8_t)bnq(acc[nb][1], sAf[cb], sBf[cb], cm);
            sS[ca * 116 + pr1] = (int8_t)bnq(acc[nb][2], sAf[ca], sBf[ca], cm);
            sS[cb * 116 + pr1] = (int8_t)bnq(acc[nb][3], sAf[cb], sBf[cb], cm);
        }
        __syncthreads();

        int pix0 = (tile0 + tl) * 112;
        int n = pix0 / P_;
        int yy = (pix0 % P_) / W_;
#pragma unroll
        for (int it = 0; it < 9; it++) {
            int i = t + it * 224;
            int co = i / 28, rem = i % 28, seg = rem / 7, wd = rem % 7;
            int val = *reinterpret_cast<const int*>(&sS[co * 116 + seg * 28 + wd * 4]);
            *reinterpret_cast<int*>(
                &g_q1p[(size_t)(co0 + co) * 30720 + n * 960 + (yy + seg + 1) * 32 + wd * 4]) = val;
        }
        if (tl < 3) CPWAIT0();
        __syncthreads();
    }
}

// ---------------- kernel: depthwise 3x3 + bn2 + relu6 + quant -> permuted g_q2 ----------------
__global__ __launch_bounds__(288) void k_dw()
{
    __shared__ __align__(16) int s_in[72 * 52];
    __shared__ __align__(16) int s_out[2016];
    int t  = threadIdx.x;
    int b  = blockIdx.x;
    int cg = b & 7;
    int s  = (b >> 3) % 7;
    int n  = b / 56;
    int c0 = cg * 72;

    const int4* g4 = reinterpret_cast<const int4*>(g_q1p);
    int4* s4 = reinterpret_cast<int4*>(s_in);
#pragma unroll
    for (int it = 0; it < 3; it++) {
        int idx = t + it * 288;
        int c = idx / 12, r4 = idx % 12;
        s4[c * 13 + r4] = g4[((c0 + c) * 32 + n) * 60 + s * 8 + r4];
    }
    __syncthreads();

    int c = t % 72, y = t / 72;
    int gc = c0 + c;
    int w0 = g_qw2r[gc * 4 + 0];
    int w1 = g_qw2r[gc * 4 + 1];
    int w2 = g_qw2r[gc * 4 + 2];
    float A = g_A2[gc], Bv = g_B2[gc];
    float cm = g_c[3];

    const int4* sb = s4 + c * 13 + y * 2;
    int4 t0 = sb[0], t1 = sb[1], t2 = sb[2], t3 = sb[3], t4 = sb[4], t5 = sb[5];
    int r0[8] = {t0.x, t0.y, t0.z, t0.w, t1.x, t1.y, t1.z, t1.w};
    int r1[8] = {t2.x, t2.y, t2.z, t2.w, t3.x, t3.y, t3.z, t3.w};
    int r2[8] = {t4.x, t4.y, t4.z, t4.w, t5.x, t5.y, t5.z, t5.w};

    int8_t* so = reinterpret_cast<int8_t*>(s_out);
#pragma unroll
    for (int j = 0; j < 7; j++) {
        int p0 = j ? r0[j - 1] : 0, m0 = r0[j], q0 = r0[j + 1];
        int p1 = j ? r1[j - 1] : 0, m1 = r1[j], q1 = r1[j + 1];
        int p2 = j ? r2[j - 1] : 0, m2 = r2[j], q2 = r2[j + 1];
        int a0 = 0, a1 = 0, a2 = 0, a3 = 0;
        a0 = dpw(p0, m0, 0x5543, w0, a0);
        a1 = dpw(p0, m0, 0x6654, w0, a1);
        a2 = dpw(p0, m0, 0x7765, w0, a2);
        a3 = dpw(m0, q0, 0x4432, w0, a3);
        a0 = dpw(p1, m1, 0x5543, w1, a0);
        a1 = dpw(p1, m1, 0x6654, w1, a1);
        a2 = dpw(p1, m1, 0x7765, w1, a2);
        a3 = dpw(m1, q1, 0x4432, w1, a3);
        a0 = dpw(p2, m2, 0x5543, w2, a0);
        a1 = dpw(p2, m2, 0x6654, w2, a1);
        a2 = dpw(p2, m2, 0x7765, w2, a2);
        a3 = dpw(m2, q2, 0x4432, w2, a3);

        int pixb = (y * 28 + j * 4) * 72 + c;
        so[pixb      ] = (int8_t)bnq(a0, A, Bv, cm);
        so[pixb + 72 ] = (int8_t)bnq(a1, A, Bv, cm);
        so[pixb + 144] = (int8_t)bnq(a2, A, Bv, cm);
        so[pixb + 216] = (int8_t)bnq(a3, A, Bv, cm);
    }
    __syncthreads();

    // copy to g_q2 with k-interleaved scatter within each 8-int group
    int pbase = n * P_ + s * 112;
#pragma unroll
    for (int it = 0; it < 7; it++) {
        int idx = t + it * 288;
        int pix = idx / 18, k = idx % 18;
        int gi = cg * 18 + k;
        int jj = gi & 7;
        int dest = (gi & ~7) + ((jj < 4) ? (jj * 2) : ((jj - 4) * 2 + 1));
        g_q2[(size_t)(pbase + pix) * 144 + dest] = s_out[idx];
    }
}

// ---------------- kernel: conv3 — W resident in smem, A via direct LDG.64, no K-loop barriers ----------------
// smem ints: W [48][148] @0 (7104), stage fp32 [48][113] @7104 (5424), floats @12528 (96)
#define C3W_STRIDE 148
#define C3STG 7104
#define C3FLT 12528
#define C3_SMEM ((12528 + 96) * 4)

__global__ __launch_bounds__(224, 4) void k_conv3m(const float* __restrict__ x,
                                                   float* __restrict__ out)
{
    extern __shared__ __align__(16) int sU[];
    uint32_t sb = smem_u32(sU);
    float* stg = reinterpret_cast<float*>(sU + C3STG);
    float* sAf = reinterpret_cast<float*>(sU + C3FLT);
    float* sBf = sAf + 48;

    int t = threadIdx.x, w = t >> 5, lane = t & 31;
    int q = lane >> 2, rr = lane & 3;
    int pix0 = blockIdx.x * 112;
    int co0  = blockIdx.y * 48;

    // load all of W (48 x 144 ints = 1728 int4) once, async
    {
#pragma unroll
        for (int it = 0; it < 8; it++) {
            int i = t + it * 224;
            if (i < 1728) {
                int r = i / 36, c = i % 36;
                cpa16(sb + (uint32_t)(r * C3W_STRIDE + c * 4) * 4,
                      g_qw3 + (size_t)(co0 + r) * 144 + c * 4);
            }
        }
        CPCOMMIT();
    }
    if (t < 48) { sAf[t] = g_A3[co0 + t]; sBf[t] = g_B3[co0 + t]; }
    CPWAIT0();
    __syncthreads();

    int acc[6][4];
#pragma unroll
    for (int nb = 0; nb < 6; nb++)
#pragma unroll
        for (int j = 0; j < 4; j++) acc[nb][j] = 0;

    // A fragments straight from global (L2): 8B LDG pairs
    const int* gA = g_q2 + (size_t)(pix0 + w * 16 + q) * 144 + 2 * rr;

#pragma unroll
    for (int ch = 0; ch < 6; ch++) {
        int2 lo[3], hi[3];
#pragma unroll
        for (int k = 0; k < 3; k++) {
            lo[k] = __ldg(reinterpret_cast<const int2*>(gA + ch * 24 + k * 8));
            hi[k] = __ldg(reinterpret_cast<const int2*>(gA + 8 * 144 + ch * 24 + k * 8));
        }
#pragma unroll
        for (int k = 0; k < 3; k++) {
#pragma unroll
            for (int nb = 0; nb < 6; nb++) {
                int2 bb = *reinterpret_cast<const int2*>(
                    sU + (nb * 8 + q) * C3W_STRIDE + 2 * rr + ch * 24 + k * 8);
                mma8(acc[nb], lo[k].x, hi[k].x, lo[k].y, hi[k].y, bb.x, bb.y);
            }
        }
    }
    __syncthreads();

    // stage fp32 [co][pix] stride 113
    int pr0 = w * 16 + q, pr1 = pr0 + 8;
#pragma unroll
    for (int nb = 0; nb < 6; nb++) {
        int ca = nb * 8 + rr * 2, cb = ca + 1;
        stg[ca * 113 + pr0] = (float)acc[nb][0];
        stg[cb * 113 + pr0] = (float)acc[nb][1];
        stg[ca * 113 + pr1] = (float)acc[nb][2];
        stg[cb * 113 + pr1] = (float)acc[nb][3];
    }
    __syncthreads();

    int n = pix0 / P_;
    int prow = pix0 % P_;
#pragma unroll
    for (int it = 0; it < 24; it++) {
        int i = t + it * 224;
        int co = i / 112, p = i % 112;
        int off = (n * C_ + co0 + co) * P_ + prow + p;
        out[off] = x[off] + fmaf(stg[co * 113 + p], sAf[co], sBf[co]);
    }
}

// ---------------- launch ----------------
extern "C" void kernel_launch(void* const* d_in, const int* in_sizes, int n_in,
                              void* d_out, int out_size)
{
    const float* x   = (const float*)d_in[0];
    const float* w1  = (const float*)d_in[1];
    const float* w2  = (const float*)d_in[2];
    const float* w3  = (const float*)d_in[3];
    const float* aw1 = (const float*)d_in[4];
    const float* ax1 = (const float*)d_in[5];
    const float* g1  = (const float*)d_in[6];
    const float* b1  = (const float*)d_in[7];
    const float* m1  = (const float*)d_in[8];
    const float* v1  = (const float*)d_in[9];
    const float* aw2 = (const float*)d_in[10];
    const float* ax2 = (const float*)d_in[11];
    const float* g2  = (const float*)d_in[12];
    const float* b2  = (const float*)d_in[13];
    const float* m2  = (const float*)d_in[14];
    const float* v2  = (const float*)d_in[15];
    const float* aw3 = (const float*)d_in[16];
    const float* ax3 = (const float*)d_in[17];
    const float* g3  = (const float*)d_in[18];
    const float* b3  = (const float*)d_in[19];
    const float* m3  = (const float*)d_in[20];
    const float* v3  = (const float*)d_in[21];
    float* out = (float*)d_out;

    cudaFuncSetAttribute(k_conv3m, cudaFuncAttributeMaxDynamicSharedMemorySize, C3_SMEM);

    k_prep<<<B_ * 25, 256>>>(x, w1, w2, w3, aw1, ax1, g1, b1, m1, v1,
                             aw2, ax2, g2, b2, m2, v2, aw3, ax3, g3, b3, m3, v3);
    k_conv1m<<<dim3(56, 8), 224>>>();
    k_dw<<<1792, 288>>>();
    k_conv3m<<<dim3(NP_ / 112, 2), 224, C3_SMEM>>>(x, out);
}

// round 14
// speedup vs baseline: 1.9063x; 1.0264x over previous
#include <cuda_runtime.h>
#include <cuda_bf16.h>
#include <cstdint>

// Problem constants
#define B_   32
#define C_   96
#define HID_ 576
#define H_   28
#define W_   28
#define P_   784
#define NP_  25088

// ---------------- device scratch ----------------
__device__ __align__(16) int8_t g_qxt[NP_ * C_];              // [pix][96] int8
__device__ __align__(16) int8_t g_q1p[HID_ * B_ * 30 * 32];   // planar halo layout
__device__ __align__(16) int8_t g_q2 [NP_ * HID_];            // [pix][576] int8
__device__ __align__(16) int8_t g_qw1[HID_ * C_];             // [co][96]
__device__ __align__(16) int8_t g_qw3[C_ * HID_];             // [co][576]
__device__ __align__(16) int    g_qw2r[HID_ * 4];
__device__ __align__(16) float  g_A1[HID_], g_B1[HID_];       // folded with 1/ax2
__device__ __align__(16) float  g_A2[HID_], g_B2[HID_];       // folded with 1/ax3
__device__ __align__(16) float  g_A3[C_],   g_B3[C_];
__device__ float g_c[4];   // [1]=min(6/ax2,7)  [3]=min(6/ax3,7)

// ---------------- helpers ----------------
__device__ __forceinline__ void mma8(int* c, int a0, int a1, int a2, int a3,
                                     int b0, int b1) {
    asm volatile("mma.sync.aligned.m16n8k32.row.col.s32.s8.s8.s32 "
        "{%0,%1,%2,%3}, {%4,%5,%6,%7}, {%8,%9}, {%0,%1,%2,%3};"
        : "+r"(c[0]), "+r"(c[1]), "+r"(c[2]), "+r"(c[3])
        : "r"(a0), "r"(a1), "r"(a2), "r"(a3), "r"(b0), "r"(b1));
}
__device__ __forceinline__ uint32_t smem_u32(const void* p) {
    uint32_t a;
    asm("{ .reg .u64 t; cvta.to.shared.u64 t, %1; cvt.u32.u64 %0, t; }" : "=r"(a) : "l"(p));
    return a;
}
__device__ __forceinline__ void cpa16(uint32_t s, const void* g) {
    asm volatile("cp.async.cg.shared.global [%0], [%1], 16;" :: "r"(s), "l"(g));
}
#define CPCOMMIT() asm volatile("cp.async.commit_group;" ::: "memory")
#define CPWAIT0()  asm volatile("cp.async.wait_group 0;" ::: "memory")

__device__ __forceinline__ int dpw(int lo, int hi, int sel, int w, int acc) {
    return __dp4a((int)__byte_perm((unsigned)lo, (unsigned)hi, (unsigned)sel), w, acc);
}
// folded epilogue: rint(clamp(acc*A + B, 0, cm))
__device__ __forceinline__ int bnq(int acc, float A, float Bv, float cm) {
    float f = fmaf((float)acc, A, Bv);
    f = fminf(fmaxf(f, 0.0f), cm);
    return (int)rintf(f);
}

// ---------------- kernel: prep = setup + halo zero + quantize/transpose x ----------------
__global__ void k_prep(const float* __restrict__ x,
                       const float* w1, const float* w2, const float* w3,
                       const float* aw1, const float* ax1,
                       const float* g1, const float* b1, const float* m1, const float* v1,
                       const float* aw2, const float* ax2,
                       const float* g2, const float* b2, const float* m2, const float* v2,
                       const float* aw3, const float* ax3,
                       const float* g3, const float* b3, const float* m3, const float* v3)
{
    __shared__ int8_t sq[C_ * 36];
    int t   = threadIdx.x;
    int tid = blockIdx.x * 256 + t;
    int nt  = gridDim.x * 256;
    float a1 = aw1[0], a2 = aw2[0], a3 = aw3[0];

    if (tid < HID_ * B_) {
        int4* p4 = reinterpret_cast<int4*>(g_q1p + (size_t)tid * 960);
        int4 z = make_int4(0, 0, 0, 0);
        p4[0] = z; p4[1] = z;
        p4[58] = z; p4[59] = z;
        int* pi = reinterpret_cast<int*>(g_q1p + (size_t)tid * 960);
#pragma unroll
        for (int r = 1; r < 29; r++) pi[r * 8 + 7] = 0;
    }
    for (int i = tid; i < HID_ * C_; i += nt)
        g_qw1[i] = (int8_t)(int)rintf(fminf(fmaxf(w1[i] / a1, -8.0f), 7.0f));
    for (int i = tid; i < C_ * HID_; i += nt)
        g_qw3[i] = (int8_t)(int)rintf(fminf(fmaxf(w3[i] / a3, -8.0f), 7.0f));
    for (int c = tid; c < HID_; c += nt) {
        int q[9];
#pragma unroll
        for (int tp = 0; tp < 9; tp++)
            q[tp] = (int)rintf(fminf(fmaxf(w2[c * 9 + tp] / a2, -8.0f), 7.0f));
#pragma unroll
        for (int r = 0; r < 3; r++)
            g_qw2r[c * 4 + r] = (q[3*r] & 255) | ((q[3*r+1] & 255) << 8) | ((q[3*r+2] & 255) << 16);
        float r2 = 1.0f / ax2[0];
        float r3 = 1.0f / ax3[0];
        float s1 = g1[c] / sqrtf(v1[c] + 1e-5f);
        g_A1[c] = ax1[0] * a1 * s1 * r2;
        g_B1[c] = (b1[c] - m1[c] * s1) * r2;
        float s2 = g2[c] / sqrtf(v2[c] + 1e-5f);
        g_A2[c] = ax2[0] * a2 * s2 * r3;
        g_B2[c] = (b2[c] - m2[c] * s2) * r3;
    }
    for (int c = tid; c < C_; c += nt) {
        float s3 = g3[c] / sqrtf(v3[c] + 1e-5f);
        g_A3[c] = ax3[0] * a3 * s3;
        g_B3[c] = b3[c] - m3[c] * s3;
    }
    if (tid == 0) {
        g_c[1] = fminf(6.0f / ax2[0], 7.0f);
        g_c[3] = fminf(6.0f / ax3[0], 7.0f);
    }

    int n  = blockIdx.x / 25;
    int p0 = (blockIdx.x % 25) * 32;
    float rax = 1.0f / ax1[0];
#pragma unroll
    for (int r = 0; r < 12; r++) {
        int idx = t + r * 256;
        int c = idx >> 5, j = idx & 31;
        int p = p0 + j;
        float val = (p < P_) ? x[(n * C_ + c) * P_ + p] : 0.0f;
        float q = rintf(fminf(fmaxf(val * rax, -8.0f), 7.0f));
        sq[c * 36 + j] = (int8_t)(int)q;
    }
    __syncthreads();
#pragma unroll
    for (int r = 0; r < 3; r++) {
        int idx = t + r * 256;
        int j = idx / 24, ii = idx % 24;
        int p = p0 + j;
        if (p < P_) {
            int b0 = (int)sq[(ii * 4 + 0) * 36 + j] & 255;
            int b1v = (int)sq[(ii * 4 + 1) * 36 + j] & 255;
            int b2v = (int)sq[(ii * 4 + 2) * 36 + j] & 255;
            int b3v = (int)sq[(ii * 4 + 3) * 36 + j] & 255;
            reinterpret_cast<int*>(g_qxt)[(n * P_ + p) * 24 + ii] =
                b0 | (b1v << 8) | (b2v << 16) | (b3v << 24);
        }
    }
}

// ---------------- kernel: conv1 via mma.sync, single wave, 4 pix-tiles/block ----------------
#define C1A(buf) ((buf) * 3136)
#define C1W      6272
#define C1STG    8288
#define C1FLT    10376
__global__ __launch_bounds__(224, 4) void k_conv1m()
{
    __shared__ __align__(16) int sU[10520];
    uint32_t sb = smem_u32(sU);
    int8_t* sS = reinterpret_cast<int8_t*>(sU + C1STG);
    float* sAf = reinterpret_cast<float*>(sU + C1FLT);
    float* sBf = sAf + 72;

    int t = threadIdx.x, w = t >> 5, lane = t & 31;
    int q = lane >> 2, rr = lane & 3;
    int tile0 = blockIdx.x * 4;
    int co0   = blockIdx.y * 72;

    {
#pragma unroll
        for (int it = 0; it < 2; it++) {
            int i = t + it * 224;
            if (i < 432) {
                int r = i / 6, c = i % 6;
                cpa16(sb + (uint32_t)(C1W + r * 28 + c * 4) * 4,
                      g_qw1 + (size_t)(co0 + r) * 96 + c * 16);
            }
        }
#pragma unroll
        for (int it = 0; it < 3; it++) {
            int i = t + it * 224;
            int r = i / 6, c = i % 6;
            cpa16(sb + (uint32_t)(C1A(0) + r * 28 + c * 4) * 4,
                  g_qxt + (size_t)(tile0 * 112 + r) * 96 + c * 16);
        }
        CPCOMMIT();
    }
    if (t < 72) { sAf[t] = g_A1[co0 + t]; sBf[t] = g_B1[co0 + t]; }
    float cm = g_c[1];
    CPWAIT0();
    __syncthreads();

#pragma unroll
    for (int tl = 0; tl < 4; tl++) {
        int buf = tl & 1;
        if (tl < 3) {
#pragma unroll
            for (int it = 0; it < 3; it++) {
                int i = t + it * 224;
                int r = i / 6, c = i % 6;
                cpa16(sb + (uint32_t)(C1A(buf ^ 1) + r * 28 + c * 4) * 4,
                      g_qxt + (size_t)((tile0 + tl + 1) * 112 + r) * 96 + c * 16);
            }
            CPCOMMIT();
        }

        int acc[9][4];
#pragma unroll
        for (int nb = 0; nb < 9; nb++)
#pragma unroll
            for (int j = 0; j < 4; j++) acc[nb][j] = 0;

        const int* ap = sU + C1A(buf) + (w * 16 + q) * 28 + rr;
#pragma unroll
        for (int k = 0; k < 3; k++) {
            int a0 = ap[k * 8];
            int a1 = ap[k * 8 + 8 * 28];
            int a2 = ap[k * 8 + 4];
            int a3 = ap[k * 8 + 8 * 28 + 4];
#pragma unroll
            for (int nb = 0; nb < 9; nb++) {
                const int* bp = sU + C1W + (nb * 8 + q) * 28 + rr + k * 8;
                mma8(acc[nb], a0, a1, a2, a3, bp[0], bp[4]);
            }
        }

        int pr0 = w * 16 + q, pr1 = pr0 + 8;
#pragma unroll
        for (int nb = 0; nb < 9; nb++) {
            int ca = nb * 8 + rr * 2, cb = ca + 1;
            sS[ca * 116 + pr0] = (int8_t)bnq(acc[nb][0], sAf[ca], sBf[ca], cm);
            sS[cb * 116 + pr0] = (int8_t)bnq(acc[nb][1], sAf[cb], sBf[cb], cm);
            sS[ca * 116 + pr1] = (int8_t)bnq(acc[nb][2], sAf[ca], sBf[ca], cm);
            sS[cb * 116 + pr1] = (int8_t)bnq(acc[nb][3], sAf[cb], sBf[cb], cm);
        }
        __syncthreads();

        int pix0 = (tile0 + tl) * 112;
        int n = pix0 / P_;
        int yy = (pix0 % P_) / W_;
#pragma unroll
        for (int it = 0; it < 9; it++) {
            int i = t + it * 224;
            int co = i / 28, rem = i % 28, seg = rem / 7, wd = rem % 7;
            int val = *reinterpret_cast<const int*>(&sS[co * 116 + seg * 28 + wd * 4]);
            *reinterpret_cast<int*>(
                &g_q1p[(size_t)(co0 + co) * 30720 + n * 960 + (yy + seg + 1) * 32 + wd * 4]) = val;
        }
        if (tl < 3) CPWAIT0();
        __syncthreads();
    }
}

// ---------------- kernel: depthwise 3x3 + bn2 + relu6 + quant ----------------
__global__ __launch_bounds__(288) void k_dw()
{
    __shared__ __align__(16) int s_in[72 * 52];
    __shared__ __align__(16) int s_out[2016];
    int t  = threadIdx.x;
    int b  = blockIdx.x;
    int cg = b & 7;
    int s  = (b >> 3) % 7;
    int n  = b / 56;
    int c0 = cg * 72;

    const int4* g4 = reinterpret_cast<const int4*>(g_q1p);
    int4* s4 = reinterpret_cast<int4*>(s_in);
#pragma unroll
    for (int it = 0; it < 3; it++) {
        int idx = t + it * 288;
        int c = idx / 12, r4 = idx % 12;
        s4[c * 13 + r4] = g4[((c0 + c) * 32 + n) * 60 + s * 8 + r4];
    }
    __syncthreads();

    int c = t % 72, y = t / 72;
    int gc = c0 + c;
    int w0 = g_qw2r[gc * 4 + 0];
    int w1 = g_qw2r[gc * 4 + 1];
    int w2 = g_qw2r[gc * 4 + 2];
    float A = g_A2[gc], Bv = g_B2[gc];
    float cm = g_c[3];

    const int4* sb = s4 + c * 13 + y * 2;
    int4 t0 = sb[0], t1 = sb[1], t2 = sb[2], t3 = sb[3], t4 = sb[4], t5 = sb[5];
    int r0[8] = {t0.x, t0.y, t0.z, t0.w, t1.x, t1.y, t1.z, t1.w};
    int r1[8] = {t2.x, t2.y, t2.z, t2.w, t3.x, t3.y, t3.z, t3.w};
    int r2[8] = {t4.x, t4.y, t4.z, t4.w, t5.x, t5.y, t5.z, t5.w};

    int8_t* so = reinterpret_cast<int8_t*>(s_out);
#pragma unroll
    for (int j = 0; j < 7; j++) {
        int p0 = j ? r0[j - 1] : 0, m0 = r0[j], q0 = r0[j + 1];
        int p1 = j ? r1[j - 1] : 0, m1 = r1[j], q1 = r1[j + 1];
        int p2 = j ? r2[j - 1] : 0, m2 = r2[j], q2 = r2[j + 1];
        int a0 = 0, a1 = 0, a2 = 0, a3 = 0;
        a0 = dpw(p0, m0, 0x5543, w0, a0);
        a1 = dpw(p0, m0, 0x6654, w0, a1);
        a2 = dpw(p0, m0, 0x7765, w0, a2);
        a3 = dpw(m0, q0, 0x4432, w0, a3);
        a0 = dpw(p1, m1, 0x5543, w1, a0);
        a1 = dpw(p1, m1, 0x6654, w1, a1);
        a2 = dpw(p1, m1, 0x7765, w1, a2);
        a3 = dpw(m1, q1, 0x4432, w1, a3);
        a0 = dpw(p2, m2, 0x5543, w2, a0);
        a1 = dpw(p2, m2, 0x6654, w2, a1);
        a2 = dpw(p2, m2, 0x7765, w2, a2);
        a3 = dpw(m2, q2, 0x4432, w2, a3);

        int pixb = (y * 28 + j * 4) * 72 + c;
        so[pixb      ] = (int8_t)bnq(a0, A, Bv, cm);
        so[pixb + 72 ] = (int8_t)bnq(a1, A, Bv, cm);
        so[pixb + 144] = (int8_t)bnq(a2, A, Bv, cm);
        so[pixb + 216] = (int8_t)bnq(a3, A, Bv, cm);
    }
    __syncthreads();

    int pbase = n * P_ + s * 112;
    int* gq2 = reinterpret_cast<int*>(g_q2);
#pragma unroll
    for (int it = 0; it < 7; it++) {
        int idx = t + it * 288;
        int pix = idx / 18, k = idx % 18;
        gq2[(pbase + pix) * 144 + cg * 18 + k] = s_out[idx];
    }
}

// ---------------- kernel: conv3 — W resident, A via register-double-buffered LDG ----------------
// 112 pix x 48 co, K=576 in 6 chunks; 7 warps each m16 x n48 (6 nb); no K-loop barriers.
// smem ints: W [48][148] @0 (7104), stage fp32 [48][113] @7104 (5424), floats @12528 (96)
#define C3W_STRIDE 148
#define C3STG 7104
#define C3FLT 12528
#define C3_SMEM ((12528 + 96) * 4)

__global__ __launch_bounds__(224, 3) void k_conv3m(const float* __restrict__ x,
                                                   float* __restrict__ out)
{
    extern __shared__ __align__(16) int sU[];
    uint32_t sb = smem_u32(sU);
    float* stg = reinterpret_cast<float*>(sU + C3STG);
    float* sAf = reinterpret_cast<float*>(sU + C3FLT);
    float* sBf = sAf + 48;

    int t = threadIdx.x, w = t >> 5, lane = t & 31;
    int q = lane >> 2, rr = lane & 3;
    int pix0 = blockIdx.x * 112;
    int co0  = blockIdx.y * 48;

    // load all of W (48 x 576B = 1728 int4) once, async
    {
#pragma unroll
        for (int it = 0; it < 8; it++) {
            int i = t + it * 224;
            if (i < 1728) {
                int r = i / 36, c = i % 36;
                cpa16(sb + (uint32_t)(r * C3W_STRIDE + c * 4) * 4,
                      g_qw3 + (size_t)(co0 + r) * HID_ + c * 16);
            }
        }
        CPCOMMIT();
    }
    if (t < 48) { sAf[t] = g_A3[co0 + t]; sBf[t] = g_B3[co0 + t]; }
    CPWAIT0();
    __syncthreads();

    int acc[6][4];
#pragma unroll
    for (int nb = 0; nb < 6; nb++)
#pragma unroll
        for (int j = 0; j < 4; j++) acc[nb][j] = 0;

    // A fragments straight from global (L2-resident g_q2), register double-buffered
    const int* gA = reinterpret_cast<const int*>(g_q2) + (size_t)(pix0 + w * 16 + q) * 144 + rr;

    int av0[12], av1[12];
#pragma unroll
    for (int k = 0; k < 3; k++) {           // prefetch chunk 0
        int base = k * 8;
        av0[k * 4 + 0] = __ldg(gA + base);
        av0[k * 4 + 1] = __ldg(gA + base + 8 * 144);
        av0[k * 4 + 2] = __ldg(gA + base + 4);
        av0[k * 4 + 3] = __ldg(gA + base + 8 * 144 + 4);
    }

#pragma unroll
    for (int ch = 0; ch < 6; ch++) {
        int* cur = (ch & 1) ? av1 : av0;
        int* nxt = (ch & 1) ? av0 : av1;
        if (ch < 5) {                       // prefetch chunk ch+1 BEFORE this chunk's mma
            int cb = (ch + 1) * 24;
#pragma unroll
            for (int k = 0; k < 3; k++) {
                int base = cb + k * 8;
                nxt[k * 4 + 0] = __ldg(gA + base);
                nxt[k * 4 + 1] = __ldg(gA + base + 8 * 144);
                nxt[k * 4 + 2] = __ldg(gA + base + 4);
                nxt[k * 4 + 3] = __ldg(gA + base + 8 * 144 + 4);
            }
        }
#pragma unroll
        for (int k = 0; k < 3; k++) {
#pragma unroll
            for (int nb = 0; nb < 6; nb++) {
                const int* bp = sU + (nb * 8 + q) * C3W_STRIDE + rr + ch * 24 + k * 8;
                mma8(acc[nb], cur[k*4], cur[k*4+1], cur[k*4+2], cur[k*4+3], bp[0], bp[4]);
            }
        }
    }
    __syncthreads();

    // stage fp32 [co][pix] stride 113
    int pr0 = w * 16 + q, pr1 = pr0 + 8;
#pragma unroll
    for (int nb = 0; nb < 6; nb++) {
        int ca = nb * 8 + rr * 2, cb = ca + 1;
        stg[ca * 113 + pr0] = (float)acc[nb][0];
        stg[cb * 113 + pr0] = (float)acc[nb][1];
        stg[ca * 113 + pr1] = (float)acc[nb][2];
        stg[cb * 113 + pr1] = (float)acc[nb][3];
    }
    __syncthreads();

    int n = pix0 / P_;
    int prow = pix0 % P_;
#pragma unroll
    for (int it = 0; it < 24; it++) {
        int i = t + it * 224;
        int co = i / 112, p = i % 112;
        int off = (n * C_ + co0 + co) * P_ + prow + p;
        out[off] = x[off] + fmaf(stg[co * 113 + p], sAf[co], sBf[co]);
    }
}

// ---------------- launch ----------------
extern "C" void kernel_launch(void* const* d_in, const int* in_sizes, int n_in,
                              void* d_out, int out_size)
{
    const float* x   = (const float*)d_in[0];
    const float* w1  = (const float*)d_in[1];
    const float* w2  = (const float*)d_in[2];
    const float* w3  = (const float*)d_in[3];
    const float* aw1 = (const float*)d_in[4];
    const float* ax1 = (const float*)d_in[5];
    const float* g1  = (const float*)d_in[6];
    const float* b1  = (const float*)d_in[7];
    const float* m1  = (const float*)d_in[8];
    const float* v1  = (const float*)d_in[9];
    const float* aw2 = (const float*)d_in[10];
    const float* ax2 = (const float*)d_in[11];
    const float* g2  = (const float*)d_in[12];
    const float* b2  = (const float*)d_in[13];
    const float* m2  = (const float*)d_in[14];
    const float* v2  = (const float*)d_in[15];
    const float* aw3 = (const float*)d_in[16];
    const float* ax3 = (const float*)d_in[17];
    const float* g3  = (const float*)d_in[18];
    const float* b3  = (const float*)d_in[19];
    const float* m3  = (const float*)d_in[20];
    const float* v3  = (const float*)d_in[21];
    float* out = (float*)d_out;

    cudaFuncSetAttribute(k_conv3m, cudaFuncAttributeMaxDynamicSharedMemorySize, C3_SMEM);

    k_prep<<<B_ * 25, 256>>>(x, w1, w2, w3, aw1, ax1, g1, b1, m1, v1,
                             aw2, ax2, g2, b2, m2, v2, aw3, ax3, g3, b3, m3, v3);
    k_conv1m<<<dim3(56, 8), 224>>>();
    k_dw<<<1792, 288>>>();
    k_conv3m<<<dim3(NP_ / 112, 2), 224, C3_SMEM>>>(x, out);
}

// round 15
// speedup vs baseline: 2.3968x; 1.2573x over previous
#include <cuda_runtime.h>
#include <cuda_bf16.h>
#include <cstdint>

// Problem constants
#define B_   32
#define C_   96
#define HID_ 576
#define H_   28
#define W_   28
#define P_   784
#define NP_  25088

// ---------------- device scratch ----------------
// GEMM operands now hold e4m3 bit patterns (values are exact small ints).
__device__ __align__(16) int8_t g_qxt[NP_ * C_];              // [pix][96] e4m3
__device__ __align__(16) int8_t g_q1p[HID_ * B_ * 30 * 32];   // planar halo, int8 (dw dp4a input)
__device__ __align__(16) int8_t g_q2 [NP_ * HID_];            // [pix][576] e4m3
__device__ __align__(16) int8_t g_qw1[HID_ * C_];             // [co][96] e4m3
__device__ __align__(16) int8_t g_qw3[C_ * HID_];             // [co][576] e4m3
__device__ __align__(16) int    g_qw2r[HID_ * 4];             // dw weights (int8 in ints)
__device__ __align__(16) float  g_A1[HID_], g_B1[HID_];       // folded with 1/ax2
__device__ __align__(16) float  g_A2[HID_], g_B2[HID_];       // folded with 1/ax3
__device__ __align__(16) float  g_A3[C_],   g_B3[C_];
__device__ float g_c[4];   // [1]=min(6/ax2,7)  [3]=min(6/ax3,7)

// ---------------- helpers ----------------
// FP8 (e4m3) MMA m16n8k32 with f32 accumulate — same fragment layout as s8 k32.
__device__ __forceinline__ void mma8f(float* c, int a0, int a1, int a2, int a3,
                                      int b0, int b1) {
    asm volatile("mma.sync.aligned.m16n8k32.row.col.f32.e4m3.e4m3.f32 "
        "{%0,%1,%2,%3}, {%4,%5,%6,%7}, {%8,%9}, {%0,%1,%2,%3};"
        : "+f"(c[0]), "+f"(c[1]), "+f"(c[2]), "+f"(c[3])
        : "r"(a0), "r"(a1), "r"(a2), "r"(a3), "r"(b0), "r"(b1));
}
// pack two floats (already integer-valued, |v|<=8) into 2 e4m3 bytes: hi<<8 | lo
__device__ __forceinline__ unsigned f8pack2(float hi, float lo) {
    unsigned short r;
    asm("cvt.rn.satfinite.e4m3x2.f32 %0, %1, %2;" : "=h"(r) : "f"(hi), "f"(lo));
    return (unsigned)r;
}
__device__ __forceinline__ uint32_t smem_u32(const void* p) {
    uint32_t a;
    asm("{ .reg .u64 t; cvta.to.shared.u64 t, %1; cvt.u32.u64 %0, t; }" : "=r"(a) : "l"(p));
    return a;
}
__device__ __forceinline__ void cpa16(uint32_t s, const void* g) {
    asm volatile("cp.async.cg.shared.global [%0], [%1], 16;" :: "r"(s), "l"(g));
}
#define CPCOMMIT() asm volatile("cp.async.commit_group;" ::: "memory")
#define CPWAIT0()  asm volatile("cp.async.wait_group 0;" ::: "memory")

__device__ __forceinline__ int dpw(int lo, int hi, int sel, int w, int acc) {
    return __dp4a((int)__byte_perm((unsigned)lo, (unsigned)hi, (unsigned)sel), w, acc);
}
// int-acc epilogue -> rounded float (for e4m3 emission)
__device__ __forceinline__ float bnqe(int acc, float A, float Bv, float cm) {
    float f = fmaf((float)acc, A, Bv);
    f = fminf(fmaxf(f, 0.0f), cm);
    return rintf(f);
}
// float-acc epilogue -> int (for int8 emission)
__device__ __forceinline__ int bnqf(float acc, float A, float Bv, float cm) {
    float f = fmaf(acc, A, Bv);
    f = fminf(fmaxf(f, 0.0f), cm);
    return (int)rintf(f);
}

// ---------------- kernel: prep = setup + halo zero + quantize/transpose x ----------------
__global__ void k_prep(const float* __restrict__ x,
                       const float* w1, const float* w2, const float* w3,
                       const float* aw1, const float* ax1,
                       const float* g1, const float* b1, const float* m1, const float* v1,
                       const float* aw2, const float* ax2,
                       const float* g2, const float* b2, const float* m2, const float* v2,
                       const float* aw3, const float* ax3,
                       const float* g3, const float* b3, const float* m3, const float* v3)
{
    __shared__ int8_t sq[C_ * 36];
    int t   = threadIdx.x;
    int tid = blockIdx.x * 256 + t;
    int nt  = gridDim.x * 256;
    float a1 = aw1[0], a2 = aw2[0], a3 = aw3[0];

    if (tid < HID_ * B_) {
        int4* p4 = reinterpret_cast<int4*>(g_q1p + (size_t)tid * 960);
        int4 z = make_int4(0, 0, 0, 0);
        p4[0] = z; p4[1] = z;
        p4[58] = z; p4[59] = z;
        int* pi = reinterpret_cast<int*>(g_q1p + (size_t)tid * 960);
#pragma unroll
        for (int r = 1; r < 29; r++) pi[r * 8 + 7] = 0;
    }
    // w1 -> e4m3, int-granular packing
    {
        float ra = 1.0f / a1;
        for (int i = tid; i < HID_ * 24; i += nt) {
            int co = i / 24, ii = i % 24;
            const float* wp = w1 + co * 96 + ii * 4;
            float q0 = rintf(fminf(fmaxf(wp[0] * ra, -8.0f), 7.0f));
            float q1 = rintf(fminf(fmaxf(wp[1] * ra, -8.0f), 7.0f));
            float q2 = rintf(fminf(fmaxf(wp[2] * ra, -8.0f), 7.0f));
            float q3 = rintf(fminf(fmaxf(wp[3] * ra, -8.0f), 7.0f));
            reinterpret_cast<int*>(g_qw1)[i] =
                (int)(f8pack2(q1, q0) | (f8pack2(q3, q2) << 16));
        }
    }
    // w3 -> e4m3
    {
        float ra = 1.0f / a3;
        for (int i = tid; i < C_ * 144; i += nt) {
            int co = i / 144, ii = i % 144;
            const float* wp = w3 + co * 576 + ii * 4;
            float q0 = rintf(fminf(fmaxf(wp[0] * ra, -8.0f), 7.0f));
            float q1 = rintf(fminf(fmaxf(wp[1] * ra, -8.0f), 7.0f));
            float q2 = rintf(fminf(fmaxf(wp[2] * ra, -8.0f), 7.0f));
            float q3 = rintf(fminf(fmaxf(wp[3] * ra, -8.0f), 7.0f));
            reinterpret_cast<int*>(g_qw3)[i] =
                (int)(f8pack2(q1, q0) | (f8pack2(q3, q2) << 16));
        }
    }
    for (int c = tid; c < HID_; c += nt) {
        int q[9];
#pragma unroll
        for (int tp = 0; tp < 9; tp++)
            q[tp] = (int)rintf(fminf(fmaxf(w2[c * 9 + tp] / a2, -8.0f), 7.0f));
#pragma unroll
        for (int r = 0; r < 3; r++)
            g_qw2r[c * 4 + r] = (q[3*r] & 255) | ((q[3*r+1] & 255) << 8) | ((q[3*r+2] & 255) << 16);
        float r2 = 1.0f / ax2[0];
        float r3 = 1.0f / ax3[0];
        float s1 = g1[c] / sqrtf(v1[c] + 1e-5f);
        g_A1[c] = ax1[0] * a1 * s1 * r2;
        g_B1[c] = (b1[c] - m1[c] * s1) * r2;
        float s2 = g2[c] / sqrtf(v2[c] + 1e-5f);
        g_A2[c] = ax2[0] * a2 * s2 * r3;
        g_B2[c] = (b2[c] - m2[c] * s2) * r3;
    }
    for (int c = tid; c < C_; c += nt) {
        float s3 = g3[c] / sqrtf(v3[c] + 1e-5f);
        g_A3[c] = ax3[0] * a3 * s3;
        g_B3[c] = b3[c] - m3[c] * s3;
    }
    if (tid == 0) {
        g_c[1] = fminf(6.0f / ax2[0], 7.0f);
        g_c[3] = fminf(6.0f / ax3[0], 7.0f);
    }

    // quantize x -> e4m3 bytes in sq, then transpose/pack
    int n  = blockIdx.x / 25;
    int p0 = (blockIdx.x % 25) * 32;
    float rax = 1.0f / ax1[0];
#pragma unroll
    for (int r = 0; r < 12; r++) {
        int idx = t + r * 256;
        int c = idx >> 5, j = idx & 31;
        int p = p0 + j;
        float val = (p < P_) ? x[(n * C_ + c) * P_ + p] : 0.0f;
        float q = rintf(fminf(fmaxf(val * rax, -8.0f), 7.0f));
        sq[c * 36 + j] = (int8_t)(f8pack2(q, q) & 255u);
    }
    __syncthreads();
#pragma unroll
    for (int r = 0; r < 3; r++) {
        int idx = t + r * 256;
        int j = idx / 24, ii = idx % 24;
        int p = p0 + j;
        if (p < P_) {
            int b0 = (int)sq[(ii * 4 + 0) * 36 + j] & 255;
            int b1v = (int)sq[(ii * 4 + 1) * 36 + j] & 255;
            int b2v = (int)sq[(ii * 4 + 2) * 36 + j] & 255;
            int b3v = (int)sq[(ii * 4 + 3) * 36 + j] & 255;
            reinterpret_cast<int*>(g_qxt)[(n * P_ + p) * 24 + ii] =
                b0 | (b1v << 8) | (b2v << 16) | (b3v << 24);
        }
    }
}

// ---------------- kernel: conv1 via fp8 mma, single wave, 4 pix-tiles/block ----------------
#define C1A(buf) ((buf) * 3136)
#define C1W      6272
#define C1STG    8288
#define C1FLT    10376
__global__ __launch_bounds__(224, 4) void k_conv1m()
{
    __shared__ __align__(16) int sU[10520];
    uint32_t sb = smem_u32(sU);
    int8_t* sS = reinterpret_cast<int8_t*>(sU + C1STG);
    float* sAf = reinterpret_cast<float*>(sU + C1FLT);
    float* sBf = sAf + 72;

    int t = threadIdx.x, w = t >> 5, lane = t & 31;
    int q = lane >> 2, rr = lane & 3;
    int tile0 = blockIdx.x * 4;
    int co0   = blockIdx.y * 72;

    {
#pragma unroll
        for (int it = 0; it < 2; it++) {
            int i = t + it * 224;
            if (i < 432) {
                int r = i / 6, c = i % 6;
                cpa16(sb + (uint32_t)(C1W + r * 28 + c * 4) * 4,
                      g_qw1 + (size_t)(co0 + r) * 96 + c * 16);
            }
        }
#pragma unroll
        for (int it = 0; it < 3; it++) {
            int i = t + it * 224;
            int r = i / 6, c = i % 6;
            cpa16(sb + (uint32_t)(C1A(0) + r * 28 + c * 4) * 4,
                  g_qxt + (size_t)(tile0 * 112 + r) * 96 + c * 16);
        }
        CPCOMMIT();
    }
    if (t < 72) { sAf[t] = g_A1[co0 + t]; sBf[t] = g_B1[co0 + t]; }
    float cm = g_c[1];
    CPWAIT0();
    __syncthreads();

#pragma unroll
    for (int tl = 0; tl < 4; tl++) {
        int buf = tl & 1;
        if (tl < 3) {
#pragma unroll
            for (int it = 0; it < 3; it++) {
                int i = t + it * 224;
                int r = i / 6, c = i % 6;
                cpa16(sb + (uint32_t)(C1A(buf ^ 1) + r * 28 + c * 4) * 4,
                      g_qxt + (size_t)((tile0 + tl + 1) * 112 + r) * 96 + c * 16);
            }
            CPCOMMIT();
        }

        float acc[9][4];
#pragma unroll
        for (int nb = 0; nb < 9; nb++)
#pragma unroll
            for (int j = 0; j < 4; j++) acc[nb][j] = 0.0f;

        const int* ap = sU + C1A(buf) + (w * 16 + q) * 28 + rr;
#pragma unroll
        for (int k = 0; k < 3; k++) {
            int a0 = ap[k * 8];
            int a1 = ap[k * 8 + 8 * 28];
            int a2 = ap[k * 8 + 4];
            int a3 = ap[k * 8 + 8 * 28 + 4];
#pragma unroll
            for (int nb = 0; nb < 9; nb++) {
                const int* bp = sU + C1W + (nb * 8 + q) * 28 + rr + k * 8;
                mma8f(acc[nb], a0, a1, a2, a3, bp[0], bp[4]);
            }
        }

        int pr0 = w * 16 + q, pr1 = pr0 + 8;
#pragma unroll
        for (int nb = 0; nb < 9; nb++) {
            int ca = nb * 8 + rr * 2, cb = ca + 1;
            sS[ca * 116 + pr0] = (int8_t)bnqf(acc[nb][0], sAf[ca], sBf[ca], cm);
            sS[cb * 116 + pr0] = (int8_t)bnqf(acc[nb][1], sAf[cb], sBf[cb], cm);
            sS[ca * 116 + pr1] = (int8_t)bnqf(acc[nb][2], sAf[ca], sBf[ca], cm);
            sS[cb * 116 + pr1] = (int8_t)bnqf(acc[nb][3], sAf[cb], sBf[cb], cm);
        }
        __syncthreads();

        int pix0 = (tile0 + tl) * 112;
        int n = pix0 / P_;
        int yy = (pix0 % P_) / W_;
#pragma unroll
        for (int it = 0; it < 9; it++) {
            int i = t + it * 224;
            int co = i / 28, rem = i % 28, seg = rem / 7, wd = rem % 7;
            int val = *reinterpret_cast<const int*>(&sS[co * 116 + seg * 28 + wd * 4]);
            *reinterpret_cast<int*>(
                &g_q1p[(size_t)(co0 + co) * 30720 + n * 960 + (yy + seg + 1) * 32 + wd * 4]) = val;
        }
        if (tl < 3) CPWAIT0();
        __syncthreads();
    }
}

// ---------------- kernel: depthwise 3x3 + bn2 + relu6 + quant -> e4m3 g_q2 ----------------
__global__ __launch_bounds__(288) void k_dw()
{
    __shared__ __align__(16) int s_in[72 * 52];
    __shared__ __align__(16) int s_out[2016];
    int t  = threadIdx.x;
    int b  = blockIdx.x;
    int cg = b & 7;
    int s  = (b >> 3) % 7;
    int n  = b / 56;
    int c0 = cg * 72;

    const int4* g4 = reinterpret_cast<const int4*>(g_q1p);
    int4* s4 = reinterpret_cast<int4*>(s_in);
#pragma unroll
    for (int it = 0; it < 3; it++) {
        int idx = t + it * 288;
        int c = idx / 12, r4 = idx % 12;
        s4[c * 13 + r4] = g4[((c0 + c) * 32 + n) * 60 + s * 8 + r4];
    }
    __syncthreads();

    int c = t % 72, y = t / 72;
    int gc = c0 + c;
    int w0 = g_qw2r[gc * 4 + 0];
    int w1 = g_qw2r[gc * 4 + 1];
    int w2 = g_qw2r[gc * 4 + 2];
    float A = g_A2[gc], Bv = g_B2[gc];
    float cm = g_c[3];

    const int4* sb = s4 + c * 13 + y * 2;
    int4 t0 = sb[0], t1 = sb[1], t2 = sb[2], t3 = sb[3], t4 = sb[4], t5 = sb[5];
    int r0[8] = {t0.x, t0.y, t0.z, t0.w, t1.x, t1.y, t1.z, t1.w};
    int r1[8] = {t2.x, t2.y, t2.z, t2.w, t3.x, t3.y, t3.z, t3.w};
    int r2[8] = {t4.x, t4.y, t4.z, t4.w, t5.x, t5.y, t5.z, t5.w};

    int8_t* so = reinterpret_cast<int8_t*>(s_out);
#pragma unroll
    for (int j = 0; j < 7; j++) {
        int p0 = j ? r0[j - 1] : 0, m0 = r0[j], q0 = r0[j + 1];
        int p1 = j ? r1[j - 1] : 0, m1 = r1[j], q1 = r1[j + 1];
        int p2 = j ? r2[j - 1] : 0, m2 = r2[j], q2 = r2[j + 1];
        int a0 = 0, a1 = 0, a2 = 0, a3 = 0;
        a0 = dpw(p0, m0, 0x5543, w0, a0);
        a1 = dpw(p0, m0, 0x6654, w0, a1);
        a2 = dpw(p0, m0, 0x7765, w0, a2);
        a3 = dpw(m0, q0, 0x4432, w0, a3);
        a0 = dpw(p1, m1, 0x5543, w1, a0);
        a1 = dpw(p1, m1, 0x6654, w1, a1);
        a2 = dpw(p1, m1, 0x7765, w1, a2);
        a3 = dpw(m1, q1, 0x4432, w1, a3);
        a0 = dpw(p2, m2, 0x5543, w2, a0);
        a1 = dpw(p2, m2, 0x6654, w2, a1);
        a2 = dpw(p2, m2, 0x7765, w2, a2);
        a3 = dpw(m2, q2, 0x4432, w2, a3);

        float f0 = bnqe(a0, A, Bv, cm);
        float f1 = bnqe(a1, A, Bv, cm);
        float f2 = bnqe(a2, A, Bv, cm);
        float f3 = bnqe(a3, A, Bv, cm);
        unsigned p01 = f8pack2(f1, f0);
        unsigned p23 = f8pack2(f3, f2);

        int pixb = (y * 28 + j * 4) * 72 + c;
        so[pixb      ] = (int8_t)(p01 & 255u);
        so[pixb + 72 ] = (int8_t)(p01 >> 8);
        so[pixb + 144] = (int8_t)(p23 & 255u);
        so[pixb + 216] = (int8_t)(p23 >> 8);
    }
    __syncthreads();

    int pbase = n * P_ + s * 112;
    int* gq2 = reinterpret_cast<int*>(g_q2);
#pragma unroll
    for (int it = 0; it < 7; it++) {
        int idx = t + it * 288;
        int pix = idx / 18, k = idx % 18;
        gq2[(pbase + pix) * 144 + cg * 18 + k] = s_out[idx];
    }
}

// ---------------- kernel: conv3 via fp8 mma — W resident, A reg-double-buffered LDG ----------------
#define C3W_STRIDE 148
#define C3STG 7104
#define C3FLT 12528
#define C3_SMEM ((12528 + 96) * 4)

__global__ __launch_bounds__(224, 3) void k_conv3m(const float* __restrict__ x,
                                                   float* __restrict__ out)
{
    extern __shared__ __align__(16) int sU[];
    uint32_t sb = smem_u32(sU);
    float* stg = reinterpret_cast<float*>(sU + C3STG);
    float* sAf = reinterpret_cast<float*>(sU + C3FLT);
    float* sBf = sAf + 48;

    int t = threadIdx.x, w = t >> 5, lane = t & 31;
    int q = lane >> 2, rr = lane & 3;
    int pix0 = blockIdx.x * 112;
    int co0  = blockIdx.y * 48;

    {
#pragma unroll
        for (int it = 0; it < 8; it++) {
            int i = t + it * 224;
            if (i < 1728) {
                int r = i / 36, c = i % 36;
                cpa16(sb + (uint32_t)(r * C3W_STRIDE + c * 4) * 4,
                      g_qw3 + (size_t)(co0 + r) * HID_ + c * 16);
            }
        }
        CPCOMMIT();
    }
    if (t < 48) { sAf[t] = g_A3[co0 + t]; sBf[t] = g_B3[co0 + t]; }
    CPWAIT0();
    __syncthreads();

    float acc[6][4];
#pragma unroll
    for (int nb = 0; nb < 6; nb++)
#pragma unroll
        for (int j = 0; j < 4; j++) acc[nb][j] = 0.0f;

    const int* gA = reinterpret_cast<const int*>(g_q2) + (size_t)(pix0 + w * 16 + q) * 144 + rr;

    int av0[12], av1[12];
#pragma unroll
    for (int k = 0; k < 3; k++) {
        int base = k * 8;
        av0[k * 4 + 0] = __ldg(gA + base);
        av0[k * 4 + 1] = __ldg(gA + base + 8 * 144);
        av0[k * 4 + 2] = __ldg(gA + base + 4);
        av0[k * 4 + 3] = __ldg(gA + base + 8 * 144 + 4);
    }

#pragma unroll
    for (int ch = 0; ch < 6; ch++) {
        int* cur = (ch & 1) ? av1 : av0;
        int* nxt = (ch & 1) ? av0 : av1;
        if (ch < 5) {
            int cb = (ch + 1) * 24;
#pragma unroll
            for (int k = 0; k < 3; k++) {
                int base = cb + k * 8;
                nxt[k * 4 + 0] = __ldg(gA + base);
                nxt[k * 4 + 1] = __ldg(gA + base + 8 * 144);
                nxt[k * 4 + 2] = __ldg(gA + base + 4);
                nxt[k * 4 + 3] = __ldg(gA + base + 8 * 144 + 4);
            }
        }
#pragma unroll
        for (int k = 0; k < 3; k++) {
#pragma unroll
            for (int nb = 0; nb < 6; nb++) {
                const int* bp = sU + (nb * 8 + q) * C3W_STRIDE + rr + ch * 24 + k * 8;
                mma8f(acc[nb], cur[k*4], cur[k*4+1], cur[k*4+2], cur[k*4+3], bp[0], bp[4]);
            }
        }
    }
    __syncthreads();

    // stage fp32 [co][pix] stride 113
    int pr0 = w * 16 + q, pr1 = pr0 + 8;
#pragma unroll
    for (int nb = 0; nb < 6; nb++) {
        int ca = nb * 8 + rr * 2, cb = ca + 1;
        stg[ca * 113 + pr0] = acc[nb][0];
        stg[cb * 113 + pr0] = acc[nb][1];
        stg[ca * 113 + pr1] = acc[nb][2];
        stg[cb * 113 + pr1] = acc[nb][3];
    }
    __syncthreads();

    int n = pix0 / P_;
    int prow = pix0 % P_;
#pragma unroll
    for (int it = 0; it < 24; it++) {
        int i = t + it * 224;
        int co = i / 112, p = i % 112;
        int off = (n * C_ + co0 + co) * P_ + prow + p;
        out[off] = x[off] + fmaf(stg[co * 113 + p], sAf[co], sBf[co]);
    }
}

// ---------------- launch ----------------
extern "C" void kernel_launch(void* const* d_in, const int* in_sizes, int n_in,
                              void* d_out, int out_size)
{
    const float* x   = (const float*)d_in[0];
    const float* w1  = (const float*)d_in[1];
    const float* w2  = (const float*)d_in[2];
    const float* w3  = (const float*)d_in[3];
    const float* aw1 = (const float*)d_in[4];
    const float* ax1 = (const float*)d_in[5];
    const float* g1  = (const float*)d_in[6];
    const float* b1  = (const float*)d_in[7];
    const float* m1  = (const float*)d_in[8];
    const float* v1  = (const float*)d_in[9];
    const float* aw2 = (const float*)d_in[10];
    const float* ax2 = (const float*)d_in[11];
    const float* g2  = (const float*)d_in[12];
    const float* b2  = (const float*)d_in[13];
    const float* m2  = (const float*)d_in[14];
    const float* v2  = (const float*)d_in[15];
    const float* aw3 = (const float*)d_in[16];
    const float* ax3 = (const float*)d_in[17];
    const float* g3  = (const float*)d_in[18];
    const float* b3  = (const float*)d_in[19];
    const float* m3  = (const float*)d_in[20];
    const float* v3  = (const float*)d_in[21];
    float* out = (float*)d_out;

    cudaFuncSetAttribute(k_conv3m, cudaFuncAttributeMaxDynamicSharedMemorySize, C3_SMEM);

    k_prep<<<B_ * 25, 256>>>(x, w1, w2, w3, aw1, ax1, g1, b1, m1, v1,
                             aw2, ax2, g2, b2, m2, v2, aw3, ax3, g3, b3, m3, v3);
    k_conv1m<<<dim3(56, 8), 224>>>();
    k_dw<<<1792, 288>>>();
    k_conv3m<<<dim3(NP_ / 112, 2), 224, C3_SMEM>>>(x, out);
}

// round 16
// speedup vs baseline: 2.3980x; 1.0005x over previous
#include <cuda_runtime.h>
#include <cuda_bf16.h>
#include <cstdint>

// Problem constants
#define B_   32
#define C_   96
#define HID_ 576
#define H_   28
#define W_   28
#define P_   784
#define NP_  25088

// ---------------- device scratch ----------------
// GEMM operands hold e4m3 bit patterns (values are exact small ints).
__device__ __align__(16) int8_t g_qxt[NP_ * C_];              // [pix][96] e4m3
__device__ __align__(16) int8_t g_q1p[HID_ * B_ * 30 * 32];   // planar halo, int8 (dw dp4a input)
__device__ __align__(16) int8_t g_q2 [NP_ * HID_];            // [pix][576] e4m3
__device__ __align__(16) int8_t g_qw1[HID_ * C_];             // [co][96] e4m3
__device__ __align__(16) int8_t g_qw3[C_ * HID_];             // [co][576] e4m3
__device__ __align__(16) int    g_qw2r[HID_ * 4];             // dw weights (int8 in ints)
__device__ __align__(16) float  g_A1[HID_], g_B1[HID_];       // folded with 1/ax2
__device__ __align__(16) float  g_A2[HID_], g_B2[HID_];       // folded with 1/ax3
__device__ __align__(16) float  g_A3[C_],   g_B3[C_];
__device__ float g_c[4];   // [1]=min(6/ax2,7)  [3]=min(6/ax3,7)

// ---------------- helpers ----------------
__device__ __forceinline__ void mma8f(float* c, int a0, int a1, int a2, int a3,
                                      int b0, int b1) {
    asm volatile("mma.sync.aligned.m16n8k32.row.col.f32.e4m3.e4m3.f32 "
        "{%0,%1,%2,%3}, {%4,%5,%6,%7}, {%8,%9}, {%0,%1,%2,%3};"
        : "+f"(c[0]), "+f"(c[1]), "+f"(c[2]), "+f"(c[3])
        : "r"(a0), "r"(a1), "r"(a2), "r"(a3), "r"(b0), "r"(b1));
}
__device__ __forceinline__ unsigned f8pack2(float hi, float lo) {
    unsigned short r;
    asm("cvt.rn.satfinite.e4m3x2.f32 %0, %1, %2;" : "=h"(r) : "f"(hi), "f"(lo));
    return (unsigned)r;
}
__device__ __forceinline__ uint32_t smem_u32(const void* p) {
    uint32_t a;
    asm("{ .reg .u64 t; cvta.to.shared.u64 t, %1; cvt.u32.u64 %0, t; }" : "=r"(a) : "l"(p));
    return a;
}
__device__ __forceinline__ void cpa16(uint32_t s, const void* g) {
    asm volatile("cp.async.cg.shared.global [%0], [%1], 16;" :: "r"(s), "l"(g));
}
#define CPCOMMIT() asm volatile("cp.async.commit_group;" ::: "memory")
#define CPWAIT0()  asm volatile("cp.async.wait_group 0;" ::: "memory")

__device__ __forceinline__ int dpw(int lo, int hi, int sel, int w, int acc) {
    return __dp4a((int)__byte_perm((unsigned)lo, (unsigned)hi, (unsigned)sel), w, acc);
}
__device__ __forceinline__ float bnqe(int acc, float A, float Bv, float cm) {
    float f = fmaf((float)acc, A, Bv);
    f = fminf(fmaxf(f, 0.0f), cm);
    return rintf(f);
}
__device__ __forceinline__ int bnqf(float acc, float A, float Bv, float cm) {
    float f = fmaf(acc, A, Bv);
    f = fminf(fmaxf(f, 0.0f), cm);
    return (int)rintf(f);
}

// ---------------- kernel: prep = setup + halo zero + quantize/transpose x ----------------
__global__ void k_prep(const float* __restrict__ x,
                       const float* w1, const float* w2, const float* w3,
                       const float* aw1, const float* ax1,
                       const float* g1, const float* b1, const float* m1, const float* v1,
                       const float* aw2, const float* ax2,
                       const float* g2, const float* b2, const float* m2, const float* v2,
                       const float* aw3, const float* ax3,
                       const float* g3, const float* b3, const float* m3, const float* v3)
{
    __shared__ int8_t sq[C_ * 36];
    int t   = threadIdx.x;
    int tid = blockIdx.x * 256 + t;
    int nt  = gridDim.x * 256;
    float a1 = aw1[0], a2 = aw2[0], a3 = aw3[0];

    if (tid < HID_ * B_) {
        int4* p4 = reinterpret_cast<int4*>(g_q1p + (size_t)tid * 960);
        int4 z = make_int4(0, 0, 0, 0);
        p4[0] = z; p4[1] = z;
        p4[58] = z; p4[59] = z;
        int* pi = reinterpret_cast<int*>(g_q1p + (size_t)tid * 960);
#pragma unroll
        for (int r = 1; r < 29; r++) pi[r * 8 + 7] = 0;
    }
    {
        float ra = 1.0f / a1;
        for (int i = tid; i < HID_ * 24; i += nt) {
            int co = i / 24, ii = i % 24;
            const float* wp = w1 + co * 96 + ii * 4;
            float q0 = rintf(fminf(fmaxf(wp[0] * ra, -8.0f), 7.0f));
            float q1 = rintf(fminf(fmaxf(wp[1] * ra, -8.0f), 7.0f));
            float q2 = rintf(fminf(fmaxf(wp[2] * ra, -8.0f), 7.0f));
            float q3 = rintf(fminf(fmaxf(wp[3] * ra, -8.0f), 7.0f));
            reinterpret_cast<int*>(g_qw1)[i] =
                (int)(f8pack2(q1, q0) | (f8pack2(q3, q2) << 16));
        }
    }
    {
        float ra = 1.0f / a3;
        for (int i = tid; i < C_ * 144; i += nt) {
            int co = i / 144, ii = i % 144;
            const float* wp = w3 + co * 576 + ii * 4;
            float q0 = rintf(fminf(fmaxf(wp[0] * ra, -8.0f), 7.0f));
            float q1 = rintf(fminf(fmaxf(wp[1] * ra, -8.0f), 7.0f));
            float q2 = rintf(fminf(fmaxf(wp[2] * ra, -8.0f), 7.0f));
            float q3 = rintf(fminf(fmaxf(wp[3] * ra, -8.0f), 7.0f));
            reinterpret_cast<int*>(g_qw3)[i] =
                (int)(f8pack2(q1, q0) | (f8pack2(q3, q2) << 16));
        }
    }
    for (int c = tid; c < HID_; c += nt) {
        int q[9];
#pragma unroll
        for (int tp = 0; tp < 9; tp++)
            q[tp] = (int)rintf(fminf(fmaxf(w2[c * 9 + tp] / a2, -8.0f), 7.0f));
#pragma unroll
        for (int r = 0; r < 3; r++)
            g_qw2r[c * 4 + r] = (q[3*r] & 255) | ((q[3*r+1] & 255) << 8) | ((q[3*r+2] & 255) << 16);
        float r2 = 1.0f / ax2[0];
        float r3 = 1.0f / ax3[0];
        float s1 = g1[c] / sqrtf(v1[c] + 1e-5f);
        g_A1[c] = ax1[0] * a1 * s1 * r2;
        g_B1[c] = (b1[c] - m1[c] * s1) * r2;
        float s2 = g2[c] / sqrtf(v2[c] + 1e-5f);
        g_A2[c] = ax2[0] * a2 * s2 * r3;
        g_B2[c] = (b2[c] - m2[c] * s2) * r3;
    }
    for (int c = tid; c < C_; c += nt) {
        float s3 = g3[c] / sqrtf(v3[c] + 1e-5f);
        g_A3[c] = ax3[0] * a3 * s3;
        g_B3[c] = b3[c] - m3[c] * s3;
    }
    if (tid == 0) {
        g_c[1] = fminf(6.0f / ax2[0], 7.0f);
        g_c[3] = fminf(6.0f / ax3[0], 7.0f);
    }

    int n  = blockIdx.x / 25;
    int p0 = (blockIdx.x % 25) * 32;
    float rax = 1.0f / ax1[0];
#pragma unroll
    for (int r = 0; r < 12; r++) {
        int idx = t + r * 256;
        int c = idx >> 5, j = idx & 31;
        int p = p0 + j;
        float val = (p < P_) ? x[(n * C_ + c) * P_ + p] : 0.0f;
        float q = rintf(fminf(fmaxf(val * rax, -8.0f), 7.0f));
        sq[c * 36 + j] = (int8_t)(f8pack2(q, q) & 255u);
    }
    __syncthreads();
#pragma unroll
    for (int r = 0; r < 3; r++) {
        int idx = t + r * 256;
        int j = idx / 24, ii = idx % 24;
        int p = p0 + j;
        if (p < P_) {
            int b0 = (int)sq[(ii * 4 + 0) * 36 + j] & 255;
            int b1v = (int)sq[(ii * 4 + 1) * 36 + j] & 255;
            int b2v = (int)sq[(ii * 4 + 2) * 36 + j] & 255;
            int b3v = (int)sq[(ii * 4 + 3) * 36 + j] & 255;
            reinterpret_cast<int*>(g_qxt)[(n * P_ + p) * 24 + ii] =
                b0 | (b1v << 8) | (b2v << 16) | (b3v << 24);
        }
    }
}

// ---------------- kernel: conv1 via fp8 mma, single wave, 4 pix-tiles/block ----------------
#define C1A(buf) ((buf) * 3136)
#define C1W      6272
#define C1STG    8288
#define C1FLT    10376
__global__ __launch_bounds__(224, 4) void k_conv1m()
{
    __shared__ __align__(16) int sU[10520];
    uint32_t sb = smem_u32(sU);
    int8_t* sS = reinterpret_cast<int8_t*>(sU + C1STG);
    float* sAf = reinterpret_cast<float*>(sU + C1FLT);
    float* sBf = sAf + 72;

    int t = threadIdx.x, w = t >> 5, lane = t & 31;
    int q = lane >> 2, rr = lane & 3;
    int tile0 = blockIdx.x * 4;
    int co0   = blockIdx.y * 72;

    {
#pragma unroll
        for (int it = 0; it < 2; it++) {
            int i = t + it * 224;
            if (i < 432) {
                int r = i / 6, c = i % 6;
                cpa16(sb + (uint32_t)(C1W + r * 28 + c * 4) * 4,
                      g_qw1 + (size_t)(co0 + r) * 96 + c * 16);
            }
        }
#pragma unroll
        for (int it = 0; it < 3; it++) {
            int i = t + it * 224;
            int r = i / 6, c = i % 6;
            cpa16(sb + (uint32_t)(C1A(0) + r * 28 + c * 4) * 4,
                  g_qxt + (size_t)(tile0 * 112 + r) * 96 + c * 16);
        }
        CPCOMMIT();
    }
    if (t < 72) { sAf[t] = g_A1[co0 + t]; sBf[t] = g_B1[co0 + t]; }
    float cm = g_c[1];
    CPWAIT0();
    __syncthreads();

#pragma unroll
    for (int tl = 0; tl < 4; tl++) {
        int buf = tl & 1;
        if (tl < 3) {
#pragma unroll
            for (int it = 0; it < 3; it++) {
                int i = t + it * 224;
                int r = i / 6, c = i % 6;
                cpa16(sb + (uint32_t)(C1A(buf ^ 1) + r * 28 + c * 4) * 4,
                      g_qxt + (size_t)((tile0 + tl + 1) * 112 + r) * 96 + c * 16);
            }
            CPCOMMIT();
        }

        float acc[9][4];
#pragma unroll
        for (int nb = 0; nb < 9; nb++)
#pragma unroll
            for (int j = 0; j < 4; j++) acc[nb][j] = 0.0f;

        const int* ap = sU + C1A(buf) + (w * 16 + q) * 28 + rr;
#pragma unroll
        for (int k = 0; k < 3; k++) {
            int a0 = ap[k * 8];
            int a1 = ap[k * 8 + 8 * 28];
            int a2 = ap[k * 8 + 4];
            int a3 = ap[k * 8 + 8 * 28 + 4];
#pragma unroll
            for (int nb = 0; nb < 9; nb++) {
                const int* bp = sU + C1W + (nb * 8 + q) * 28 + rr + k * 8;
                mma8f(acc[nb], a0, a1, a2, a3, bp[0], bp[4]);
            }
        }

        int pr0 = w * 16 + q, pr1 = pr0 + 8;
#pragma unroll
        for (int nb = 0; nb < 9; nb++) {
            int ca = nb * 8 + rr * 2, cb = ca + 1;
            sS[ca * 116 + pr0] = (int8_t)bnqf(acc[nb][0], sAf[ca], sBf[ca], cm);
            sS[cb * 116 + pr0] = (int8_t)bnqf(acc[nb][1], sAf[cb], sBf[cb], cm);
            sS[ca * 116 + pr1] = (int8_t)bnqf(acc[nb][2], sAf[ca], sBf[ca], cm);
            sS[cb * 116 + pr1] = (int8_t)bnqf(acc[nb][3], sAf[cb], sBf[cb], cm);
        }
        __syncthreads();

        int pix0 = (tile0 + tl) * 112;
        int n = pix0 / P_;
        int yy = (pix0 % P_) / W_;
#pragma unroll
        for (int it = 0; it < 9; it++) {
            int i = t + it * 224;
            int co = i / 28, rem = i % 28, seg = rem / 7, wd = rem % 7;
            int val = *reinterpret_cast<const int*>(&sS[co * 116 + seg * 28 + wd * 4]);
            *reinterpret_cast<int*>(
                &g_q1p[(size_t)(co0 + co) * 30720 + n * 960 + (yy + seg + 1) * 32 + wd * 4]) = val;
        }
        if (tl < 3) CPWAIT0();
        __syncthreads();
    }
}

// ---------------- kernel: depthwise 3x3 + bn2 + relu6 + quant -> e4m3 g_q2 ----------------
__global__ __launch_bounds__(288) void k_dw()
{
    __shared__ __align__(16) int s_in[72 * 52];
    __shared__ __align__(16) int s_out[2016];
    int t  = threadIdx.x;
    int b  = blockIdx.x;
    int cg = b & 7;
    int s  = (b >> 3) % 7;
    int n  = b / 56;
    int c0 = cg * 72;

    const int4* g4 = reinterpret_cast<const int4*>(g_q1p);
    int4* s4 = reinterpret_cast<int4*>(s_in);
#pragma unroll
    for (int it = 0; it < 3; it++) {
        int idx = t + it * 288;
        int c = idx / 12, r4 = idx % 12;
        s4[c * 13 + r4] = g4[((c0 + c) * 32 + n) * 60 + s * 8 + r4];
    }
    __syncthreads();

    int c = t % 72, y = t / 72;
    int gc = c0 + c;
    int w0 = g_qw2r[gc * 4 + 0];
    int w1 = g_qw2r[gc * 4 + 1];
    int w2 = g_qw2r[gc * 4 + 2];
    float A = g_A2[gc], Bv = g_B2[gc];
    float cm = g_c[3];

    const int4* sb = s4 + c * 13 + y * 2;
    int4 t0 = sb[0], t1 = sb[1], t2 = sb[2], t3 = sb[3], t4 = sb[4], t5 = sb[5];
    int r0[8] = {t0.x, t0.y, t0.z, t0.w, t1.x, t1.y, t1.z, t1.w};
    int r1[8] = {t2.x, t2.y, t2.z, t2.w, t3.x, t3.y, t3.z, t3.w};
    int r2[8] = {t4.x, t4.y, t4.z, t4.w, t5.x, t5.y, t5.z, t5.w};

    int8_t* so = reinterpret_cast<int8_t*>(s_out);
#pragma unroll
    for (int j = 0; j < 7; j++) {
        int p0 = j ? r0[j - 1] : 0, m0 = r0[j], q0 = r0[j + 1];
        int p1 = j ? r1[j - 1] : 0, m1 = r1[j], q1 = r1[j + 1];
        int p2 = j ? r2[j - 1] : 0, m2 = r2[j], q2 = r2[j + 1];
        int a0 = 0, a1 = 0, a2 = 0, a3 = 0;
        a0 = dpw(p0, m0, 0x5543, w0, a0);
        a1 = dpw(p0, m0, 0x6654, w0, a1);
        a2 = dpw(p0, m0, 0x7765, w0, a2);
        a3 = dpw(m0, q0, 0x4432, w0, a3);
        a0 = dpw(p1, m1, 0x5543, w1, a0);
        a1 = dpw(p1, m1, 0x6654, w1, a1);
        a2 = dpw(p1, m1, 0x7765, w1, a2);
        a3 = dpw(m1, q1, 0x4432, w1, a3);
        a0 = dpw(p2, m2, 0x5543, w2, a0);
        a1 = dpw(p2, m2, 0x6654, w2, a1);
        a2 = dpw(p2, m2, 0x7765, w2, a2);
        a3 = dpw(m2, q2, 0x4432, w2, a3);

        float f0 = bnqe(a0, A, Bv, cm);
        float f1 = bnqe(a1, A, Bv, cm);
        float f2 = bnqe(a2, A, Bv, cm);
        float f3 = bnqe(a3, A, Bv, cm);
        unsigned p01 = f8pack2(f1, f0);
        unsigned p23 = f8pack2(f3, f2);

        int pixb = (y * 28 + j * 4) * 72 + c;
        so[pixb      ] = (int8_t)(p01 & 255u);
        so[pixb + 72 ] = (int8_t)(p01 >> 8);
        so[pixb + 144] = (int8_t)(p23 & 255u);
        so[pixb + 216] = (int8_t)(p23 >> 8);
    }
    __syncthreads();

    int pbase = n * P_ + s * 112;
    int* gq2 = reinterpret_cast<int*>(g_q2);
#pragma unroll
    for (int it = 0; it < 7; it++) {
        int idx = t + it * 288;
        int pix = idx / 18, k = idx % 18;
        gq2[(pbase + pix) * 144 + cg * 18 + k] = s_out[idx];
    }
}

// ---------------- kernel: conv3 via fp8 mma — W resident (stage overlays W), 4 blocks/SM ----------------
// smem ints: W [48][148] @0 (7104); stage fp32 [48][113] OVERLAYS @0 after mma; floats @7104 (96)
#define C3W_STRIDE 148
#define C3FLT 7104
#define C3_SMEM ((7104 + 96) * 4)

__global__ __launch_bounds__(224, 4) void k_conv3m(const float* __restrict__ x,
                                                   float* __restrict__ out)
{
    extern __shared__ __align__(16) int sU[];
    uint32_t sb = smem_u32(sU);
    float* stg = reinterpret_cast<float*>(sU);        // overlay after mma
    float* sAf = reinterpret_cast<float*>(sU + C3FLT);
    float* sBf = sAf + 48;

    int t = threadIdx.x, w = t >> 5, lane = t & 31;
    int q = lane >> 2, rr = lane & 3;
    int pix0 = blockIdx.x * 112;
    int co0  = blockIdx.y * 48;

    {
#pragma unroll
        for (int it = 0; it < 8; it++) {
            int i = t + it * 224;
            if (i < 1728) {
                int r = i / 36, c = i % 36;
                cpa16(sb + (uint32_t)(r * C3W_STRIDE + c * 4) * 4,
                      g_qw3 + (size_t)(co0 + r) * HID_ + c * 16);
            }
        }
        CPCOMMIT();
    }
    if (t < 48) { sAf[t] = g_A3[co0 + t]; sBf[t] = g_B3[co0 + t]; }
    CPWAIT0();
    __syncthreads();

    float acc[6][4];
#pragma unroll
    for (int nb = 0; nb < 6; nb++)
#pragma unroll
        for (int j = 0; j < 4; j++) acc[nb][j] = 0.0f;

    const int* gA = reinterpret_cast<const int*>(g_q2) + (size_t)(pix0 + w * 16 + q) * 144 + rr;

#pragma unroll
    for (int ch = 0; ch < 6; ch++) {
        int av[12];
#pragma unroll
        for (int k = 0; k < 3; k++) {
            int base = ch * 24 + k * 8;
            av[k * 4 + 0] = __ldg(gA + base);
            av[k * 4 + 1] = __ldg(gA + base + 8 * 144);
            av[k * 4 + 2] = __ldg(gA + base + 4);
            av[k * 4 + 3] = __ldg(gA + base + 8 * 144 + 4);
        }
#pragma unroll
        for (int k = 0; k < 3; k++) {
#pragma unroll
            for (int nb = 0; nb < 6; nb++) {
                const int* bp = sU + (nb * 8 + q) * C3W_STRIDE + rr + ch * 24 + k * 8;
                mma8f(acc[nb], av[k*4], av[k*4+1], av[k*4+2], av[k*4+3], bp[0], bp[4]);
            }
        }
    }
    __syncthreads();   // all warps done with W before stage overlay

    // stage fp32 [co][pix] stride 113 (overlays W region)
    int pr0 = w * 16 + q, pr1 = pr0 + 8;
#pragma unroll
    for (int nb = 0; nb < 6; nb++) {
        int ca = nb * 8 + rr * 2, cb = ca + 1;
        stg[ca * 113 + pr0] = acc[nb][0];
        stg[cb * 113 + pr0] = acc[nb][1];
        stg[ca * 113 + pr1] = acc[nb][2];
        stg[cb * 113 + pr1] = acc[nb][3];
    }
    __syncthreads();

    int n = pix0 / P_;
    int prow = pix0 % P_;
#pragma unroll
    for (int it = 0; it < 24; it++) {
        int i = t + it * 224;
        int co = i / 112, p = i % 112;
        int off = (n * C_ + co0 + co) * P_ + prow + p;
        out[off] = x[off] + fmaf(stg[co * 113 + p], sAf[co], sBf[co]);
    }
}

// ---------------- launch ----------------
extern "C" void kernel_launch(void* const* d_in, const int* in_sizes, int n_in,
                              void* d_out, int out_size)
{
    const float* x   = (const float*)d_in[0];
    const float* w1  = (const float*)d_in[1];
    const float* w2  = (const float*)d_in[2];
    const float* w3  = (const float*)d_in[3];
    const float* aw1 = (const float*)d_in[4];
    const float* ax1 = (const float*)d_in[5];
    const float* g1  = (const float*)d_in[6];
    const float* b1  = (const float*)d_in[7];
    const float* m1  = (const float*)d_in[8];
    const float* v1  = (const float*)d_in[9];
    const float* aw2 = (const float*)d_in[10];
    const float* ax2 = (const float*)d_in[11];
    const float* g2  = (const float*)d_in[12];
    const float* b2  = (const float*)d_in[13];
    const float* m2  = (const float*)d_in[14];
    const float* v2  = (const float*)d_in[15];
    const float* aw3 = (const float*)d_in[16];
    const float* ax3 = (const float*)d_in[17];
    const float* g3  = (const float*)d_in[18];
    const float* b3  = (const float*)d_in[19];
    const float* m3  = (const float*)d_in[20];
    const float* v3  = (const float*)d_in[21];
    float* out = (float*)d_out;

    cudaFuncSetAttribute(k_conv3m, cudaFuncAttributeMaxDynamicSharedMemorySize, C3_SMEM);

    k_prep<<<B_ * 25, 256>>>(x, w1, w2, w3, aw1, ax1, g1, b1, m1, v1,
                             aw2, ax2, g2, b2, m2, v2, aw3, ax3, g3, b3, m3, v3);
    k_conv1m<<<dim3(56, 8), 224>>>();
    k_dw<<<1792, 288>>>();
    k_conv3m<<<dim3(NP_ / 112, 2), 224, C3_SMEM>>>(x, out);
}